// round 5
// baseline (speedup 1.0000x reference)
#include <cuda_runtime.h>
#include <cuda_bf16.h>
#include <stdint.h>
#include <math.h>

#define B_  2
#define L_  2048
#define D_  512
#define H_  8
#define HD_ 64
#define KS_ 4          // split-K factor for the final GEMM

// ======================= scratch (device globals) ==========================
__device__ __nv_bfloat16 g_q_hi [(size_t)B_*L_*D_];
__device__ __nv_bfloat16 g_q_lo [(size_t)B_*L_*D_];
__device__ __nv_bfloat16 g_k_hi [(size_t)B_*L_*D_];
__device__ __nv_bfloat16 g_k_lo [(size_t)B_*L_*D_];
__device__ __nv_bfloat16 g_v_hi [(size_t)B_*L_*D_];
__device__ __nv_bfloat16 g_v_lo [(size_t)B_*L_*D_];
__device__ __nv_bfloat16 g_WqT_hi[(size_t)H_*D_*D_];
__device__ __nv_bfloat16 g_WqT_lo[(size_t)H_*D_*D_];
__device__ __nv_bfloat16 g_WkT_hi[(size_t)H_*D_*D_];
__device__ __nv_bfloat16 g_WkT_lo[(size_t)H_*D_*D_];
__device__ __nv_bfloat16 g_WvT_hi[(size_t)H_*D_*D_];
__device__ __nv_bfloat16 g_WvT_lo[(size_t)H_*D_*D_];
__device__ __nv_bfloat16 g_Wop_hi[(size_t)H_*D_*D_];
__device__ __nv_bfloat16 g_Wop_lo[(size_t)H_*D_*D_];
__device__ __nv_bfloat16 g_MT_hi[(size_t)H_*D_*D_];
__device__ __nv_bfloat16 g_MT_lo[(size_t)H_*D_*D_];
__device__ __nv_bfloat16 g_P_hi [(size_t)H_*D_*D_];
__device__ __nv_bfloat16 g_P_lo [(size_t)H_*D_*D_];
__device__ __nv_bfloat16 g_t_hi [(size_t)B_*H_*L_*D_];
__device__ __nv_bfloat16 g_t_lo [(size_t)B_*H_*L_*D_];
__device__ __nv_bfloat16 g_ZT_hi[(size_t)B_*D_*H_*L_];
__device__ __nv_bfloat16 g_ZT_lo[(size_t)B_*D_*H_*L_];
__device__ float         g_part [(size_t)B_*KS_*L_*D_];

// ======================= small helpers ======================================
__device__ __forceinline__ uint32_t smem_u32(const void* p) {
    uint32_t a;
    asm("{ .reg .u64 t; cvta.to.shared.u64 t, %1; cvt.u32.u64 %0, t; }"
        : "=r"(a) : "l"(p));
    return a;
}
__device__ __forceinline__ uint32_t swz(uint32_t o) { return o ^ ((o >> 3) & 0x30); }

__device__ __forceinline__ void cp16(uint32_t s, const void* g) {
    asm volatile("cp.async.cg.shared.global [%0], [%1], 16;" :: "r"(s), "l"(g));
}
#define CP_COMMIT() asm volatile("cp.async.commit_group;" ::: "memory")

__device__ __forceinline__ void ldm4(uint32_t* r, uint32_t a) {
    asm volatile("ldmatrix.sync.aligned.m8n8.x4.shared.b16 {%0,%1,%2,%3}, [%4];"
                 : "=r"(r[0]), "=r"(r[1]), "=r"(r[2]), "=r"(r[3]) : "r"(a));
}
__device__ __forceinline__ float2 lds_f2(uint32_t a) {
    float2 v;
    asm volatile("ld.shared.v2.f32 {%0,%1}, [%2];" : "=f"(v.x), "=f"(v.y) : "r"(a));
    return v;
}
__device__ __forceinline__ void mma_bf16(float* c, const uint32_t* a, const uint32_t* b) {
    asm volatile("mma.sync.aligned.m16n8k16.row.col.f32.bf16.bf16.f32 "
                 "{%0,%1,%2,%3}, {%4,%5,%6,%7}, {%8,%9}, {%0,%1,%2,%3};"
                 : "+f"(c[0]), "+f"(c[1]), "+f"(c[2]), "+f"(c[3])
                 : "r"(a[0]), "r"(a[1]), "r"(a[2]), "r"(a[3]), "r"(b[0]), "r"(b[1]));
}
__device__ __forceinline__ void split2(float x, __nv_bfloat16& h, __nv_bfloat16& l) {
    h = __float2bfloat16(x);
    l = __float2bfloat16(x - __bfloat162float(h));
}
__device__ __forceinline__ void split_pack(float2 v, uint32_t& hi, uint32_t& lo) {
    __nv_bfloat16 h0, l0, h1, l1;
    split2(v.x, h0, l0);
    split2(v.y, h1, l1);
    hi = ((uint32_t)__bfloat16_as_ushort(h1) << 16) | __bfloat16_as_ushort(h0);
    lo = ((uint32_t)__bfloat16_as_ushort(l1) << 16) | __bfloat16_as_ushort(l0);
}

// ======================= bf16x3 HMMA GEMM (4-stage pipeline) ================
// C[m,n] = alpha * sum_k A[m,k]*B[n,k]   (NT, both K-major bf16 hi/lo)
#define KC       32
#define TILE_B   (128 * 64)
#define STAGE_B  (4 * TILE_B)        // 32 KB
#define NSTAGE   4
#define SMEM_T   (NSTAGE * STAGE_B)  // 128 KB

template <int MODE>   // 0: fp32 out, 1: bf16 hi/lo out
__global__ __launch_bounds__(256, 1)
void mma_gemm(const __nv_bfloat16* __restrict__ Ahi, const __nv_bfloat16* __restrict__ Alo,
              const __nv_bfloat16* __restrict__ Bhi, const __nv_bfloat16* __restrict__ Blo,
              float* __restrict__ C, __nv_bfloat16* __restrict__ Chi,
              __nv_bfloat16* __restrict__ Clo,
              int K, int ldc, long sA, long sB,
              int adiv, int amod, int bdiv, int bmod,
              int czdiv, long sC1, int czmod, long sC2, float alpha)
{
    extern __shared__ char smem[];
    const uint32_t sb = smem_u32(smem);
    const int tid  = threadIdx.x;
    const int lane = tid & 31, wid = tid >> 5;
    const int moff = (wid & 1) * 64;
    const int noff = (wid >> 1) * 32;

    const int z = blockIdx.z;
    const __nv_bfloat16* A0h = Ahi + (long)((z / adiv) % amod) * sA;
    const __nv_bfloat16* A0l = Alo + (long)((z / adiv) % amod) * sA;
    const __nv_bfloat16* B0h = Bhi + (long)((z / bdiv) % bmod) * sB;
    const __nv_bfloat16* B0l = Blo + (long)((z / bdiv) % bmod) * sB;
    const long coff = (long)(z / czdiv) * sC1 + (long)(z % czmod) * sC2;
    const long m0 = (long)blockIdx.y * 128;
    const long n0 = (long)blockIdx.x * 128;

    float acc[4][4][4];
#pragma unroll
    for (int a = 0; a < 4; a++)
#pragma unroll
        for (int b = 0; b < 4; b++)
#pragma unroll
            for (int c = 0; c < 4; c++) acc[a][b][c] = 0.f;

    const int NC = K / KC;
    const int r0 = tid >> 2, c0 = tid & 3;
    const int r1 = (tid + 256) >> 2, c1 = tid & 3;

#define LOAD_STAGE(cidx) do {                                                   \
        const uint32_t st = sb + ((cidx) % NSTAGE) * STAGE_B;                   \
        const int k0 = (cidx) * KC;                                             \
        const long goA0 = (m0 + r0) * (long)K + k0 + c0 * 8;                    \
        const long goA1 = (m0 + r1) * (long)K + k0 + c1 * 8;                    \
        const long goB0 = (n0 + r0) * (long)K + k0 + c0 * 8;                    \
        const long goB1 = (n0 + r1) * (long)K + k0 + c1 * 8;                    \
        const uint32_t so0 = swz(r0 * 64 + c0 * 16);                            \
        const uint32_t so1 = swz(r1 * 64 + c1 * 16);                            \
        cp16(st + so0,              A0h + goA0);                                \
        cp16(st + so1,              A0h + goA1);                                \
        cp16(st + TILE_B + so0,     A0l + goA0);                                \
        cp16(st + TILE_B + so1,     A0l + goA1);                                \
        cp16(st + 2 * TILE_B + so0, B0h + goB0);                                \
        cp16(st + 2 * TILE_B + so1, B0h + goB1);                                \
        cp16(st + 3 * TILE_B + so0, B0l + goB0);                                \
        cp16(st + 3 * TILE_B + so1, B0l + goB1);                                \
    } while (0)

    LOAD_STAGE(0);
    CP_COMMIT();
    if (NC > 1) LOAD_STAGE(1);
    CP_COMMIT();
    if (NC > 2) LOAD_STAGE(2);
    CP_COMMIT();

    const int arow = (lane & 7) + ((lane >> 3) & 1) * 8;
    const int ach  = (lane >> 4);
    const int brow = (lane & 7) + ((lane >> 4) & 1) * 8;
    const int bch  = ((lane >> 3) & 1);

    for (int c = 0; c < NC; c++) {
        asm volatile("cp.async.wait_group 2;" ::: "memory");
        __syncthreads();
        if (c + 3 < NC) LOAD_STAGE(c + 3);
        CP_COMMIT();

        const uint32_t st = sb + (c % NSTAGE) * STAGE_B;
#pragma unroll
        for (int kk = 0; kk < 2; kk++) {
            uint32_t ah[4][4], al[4][4], bh[4][2], bl[4][2];
#pragma unroll
            for (int mf = 0; mf < 4; mf++) {
                uint32_t ad = st + swz((moff + mf * 16 + arow) * 64 + (kk * 2 + ach) * 16);
                ldm4(ah[mf], ad);
                ldm4(al[mf], ad + TILE_B);
            }
#pragma unroll
            for (int p = 0; p < 2; p++) {
                uint32_t bd = st + 2 * TILE_B +
                              swz((noff + p * 16 + brow) * 64 + (kk * 2 + bch) * 16);
                uint32_t r[4];
                ldm4(r, bd);
                bh[2 * p][0] = r[0]; bh[2 * p][1] = r[1];
                bh[2 * p + 1][0] = r[2]; bh[2 * p + 1][1] = r[3];
                ldm4(r, bd + TILE_B);
                bl[2 * p][0] = r[0]; bl[2 * p][1] = r[1];
                bl[2 * p + 1][0] = r[2]; bl[2 * p + 1][1] = r[3];
            }
#pragma unroll
            for (int mf = 0; mf < 4; mf++)
#pragma unroll
                for (int nf = 0; nf < 4; nf++) {
                    mma_bf16(acc[mf][nf], ah[mf], bh[nf]);
                    mma_bf16(acc[mf][nf], ah[mf], bl[nf]);
                    mma_bf16(acc[mf][nf], al[mf], bh[nf]);
                }
        }
    }
#undef LOAD_STAGE

    const int gq = lane >> 2, tg = lane & 3;
#pragma unroll
    for (int mf = 0; mf < 4; mf++)
#pragma unroll
        for (int nf = 0; nf < 4; nf++) {
            const long row = m0 + moff + mf * 16 + gq;
            const long col = n0 + noff + nf * 8 + tg * 2;
            float v0 = alpha * acc[mf][nf][0];
            float v1 = alpha * acc[mf][nf][1];
            float v2 = alpha * acc[mf][nf][2];
            float v3 = alpha * acc[mf][nf][3];
            if (MODE == 0) {
                float2 p0 = {v0, v1}, p1 = {v2, v3};
                *reinterpret_cast<float2*>(C + coff + row * ldc + col)       = p0;
                *reinterpret_cast<float2*>(C + coff + (row + 8) * ldc + col) = p1;
            } else {
                uint32_t hp0, lp0, hp1, lp1;
                split_pack({v0, v1}, hp0, lp0);
                split_pack({v2, v3}, hp1, lp1);
                *reinterpret_cast<uint32_t*>(Chi + coff + row * ldc + col)       = hp0;
                *reinterpret_cast<uint32_t*>(Clo + coff + row * ldc + col)       = lp0;
                *reinterpret_cast<uint32_t*>(Chi + coff + (row + 8) * ldc + col) = hp1;
                *reinterpret_cast<uint32_t*>(Clo + coff + (row + 8) * ldc + col) = lp1;
            }
        }
}

// =================== final GEMM: A = attn fp32 direct, split-K ==============
// part[b*KS+ks][l][e] = sum_{k in ks-range} at'[b,l,k] * ZT[b,e,k],
// at'[b,l,h*L+m] = attn[b,h,l,m] (fp32), ZT bf16 hi/lo [B, D, H*L].
#define A_ROWB   144                       // fp32 A tile row stride bytes (36 floats)
#define A_TILE_O (128 * A_ROWB)            // 18432
#define STAGE_O  (A_TILE_O + 2 * TILE_B)   // 34816
#define SMEM_O   (NSTAGE * STAGE_O)        // 139264

__global__ __launch_bounds__(256, 1)
void out_gemm(const float* __restrict__ attn,
              const __nv_bfloat16* __restrict__ Bhi, const __nv_bfloat16* __restrict__ Blo,
              float* __restrict__ part)
{
    extern __shared__ char smem[];
    const uint32_t sb = smem_u32(smem);
    const int tid  = threadIdx.x;
    const int lane = tid & 31, wid = tid >> 5;
    const int moff = (wid & 1) * 64;
    const int noff = (wid >> 1) * 32;

    const int z  = blockIdx.z;
    const int b  = z >> 2;                  // KS_ = 4
    const int ks = z & 3;
    const int kbase = ks * (H_ * L_ / KS_); // 4096
    const long m0 = (long)blockIdx.y * 128;
    const long n0 = (long)blockIdx.x * 128;

    const float* Aab = attn + (long)b * H_ * L_ * L_;
    const __nv_bfloat16* B0h = Bhi + (long)b * D_ * H_ * L_;
    const __nv_bfloat16* B0l = Blo + (long)b * D_ * H_ * L_;

    float acc[4][4][4];
#pragma unroll
    for (int a = 0; a < 4; a++)
#pragma unroll
        for (int bb = 0; bb < 4; bb++)
#pragma unroll
            for (int c = 0; c < 4; c++) acc[a][bb][c] = 0.f;

    const int NC = (H_ * L_ / KS_) / KC;    // 128

    const int ar = tid >> 1, ahalf = tid & 1;            // A: 2 thr/row, 4 cp16 each
    const int r0 = tid >> 2, c0 = tid & 3;               // B slots
    const int r1 = (tid + 256) >> 2;

#define LOAD_STAGE_O(cidx) do {                                                  \
        const uint32_t st = sb + ((cidx) % NSTAGE) * STAGE_O;                    \
        const int kg = kbase + (cidx) * KC;                                      \
        const int hh = kg >> 11, mm = kg & (L_ - 1);                             \
        const float* arow_p = Aab + ((long)hh * L_ + m0 + ar) * L_ + mm + ahalf * 16; \
        const uint32_t adst = st + ar * A_ROWB + ahalf * 64;                     \
        cp16(adst,      arow_p);                                                 \
        cp16(adst + 16, arow_p + 4);                                             \
        cp16(adst + 32, arow_p + 8);                                             \
        cp16(adst + 48, arow_p + 12);                                            \
        const long goB0 = (n0 + r0) * (long)(H_ * L_) + kg + c0 * 8;             \
        const long goB1 = (n0 + r1) * (long)(H_ * L_) + kg + c0 * 8;             \
        const uint32_t so0 = swz(r0 * 64 + c0 * 16);                             \
        const uint32_t so1 = swz(r1 * 64 + c0 * 16);                             \
        cp16(st + A_TILE_O + so0,          B0h + goB0);                          \
        cp16(st + A_TILE_O + so1,          B0h + goB1);                          \
        cp16(st + A_TILE_O + TILE_B + so0, B0l + goB0);                          \
        cp16(st + A_TILE_O + TILE_B + so1, B0l + goB1);                          \
    } while (0)

    LOAD_STAGE_O(0); CP_COMMIT();
    LOAD_STAGE_O(1); CP_COMMIT();
    LOAD_STAGE_O(2); CP_COMMIT();

    const int brow = (lane & 7) + ((lane >> 4) & 1) * 8;
    const int bch  = ((lane >> 3) & 1);
    const int aq = lane >> 2, at2 = (lane & 3) * 2;

    for (int c = 0; c < NC; c++) {
        asm volatile("cp.async.wait_group 2;" ::: "memory");
        __syncthreads();
        if (c + 3 < NC) LOAD_STAGE_O(c + 3);
        CP_COMMIT();

        const uint32_t st = sb + (c % NSTAGE) * STAGE_O;
#pragma unroll
        for (int kk = 0; kk < 2; kk++) {
            uint32_t ah[4][4], al[4][4], bh[4][2], bl[4][2];
#pragma unroll
            for (int mf = 0; mf < 4; mf++) {
                const uint32_t base = st + (moff + mf * 16 + aq) * A_ROWB
                                         + (kk * 16 + at2) * 4;
                split_pack(lds_f2(base),                 ah[mf][0], al[mf][0]);
                split_pack(lds_f2(base + 8 * A_ROWB),    ah[mf][1], al[mf][1]);
                split_pack(lds_f2(base + 32),            ah[mf][2], al[mf][2]);
                split_pack(lds_f2(base + 8 * A_ROWB + 32), ah[mf][3], al[mf][3]);
            }
#pragma unroll
            for (int p = 0; p < 2; p++) {
                uint32_t bd = st + A_TILE_O +
                              swz((noff + p * 16 + brow) * 64 + (kk * 2 + bch) * 16);
                uint32_t r[4];
                ldm4(r, bd);
                bh[2 * p][0] = r[0]; bh[2 * p][1] = r[1];
                bh[2 * p + 1][0] = r[2]; bh[2 * p + 1][1] = r[3];
                ldm4(r, bd + TILE_B);
                bl[2 * p][0] = r[0]; bl[2 * p][1] = r[1];
                bl[2 * p + 1][0] = r[2]; bl[2 * p + 1][1] = r[3];
            }
#pragma unroll
            for (int mf = 0; mf < 4; mf++)
#pragma unroll
                for (int nf = 0; nf < 4; nf++) {
                    mma_bf16(acc[mf][nf], ah[mf], bh[nf]);
                    mma_bf16(acc[mf][nf], ah[mf], bl[nf]);
                    mma_bf16(acc[mf][nf], al[mf], bh[nf]);
                }
        }
    }
#undef LOAD_STAGE_O

    float* Cb = part + (long)z * L_ * D_;
    const int gq = lane >> 2, tg = lane & 3;
#pragma unroll
    for (int mf = 0; mf < 4; mf++)
#pragma unroll
        for (int nf = 0; nf < 4; nf++) {
            const long row = m0 + moff + mf * 16 + gq;
            const long col = n0 + noff + nf * 8 + tg * 2;
            float2 p0 = {acc[mf][nf][0], acc[mf][nf][1]};
            float2 p1 = {acc[mf][nf][2], acc[mf][nf][3]};
            *reinterpret_cast<float2*>(Cb + row * D_ + col)       = p0;
            *reinterpret_cast<float2*>(Cb + (row + 8) * D_ + col) = p1;
        }
}

// reduce partials: out[b][j] = sum_ks part[b*KS+ks][j]
__global__ __launch_bounds__(256)
void reduce_part(const float4* __restrict__ part, float4* __restrict__ out)
{
    const int LD4 = L_ * D_ / 4;
    long idx = (long)blockIdx.x * 256 + threadIdx.x;     // over B*LD4
    int b = (int)(idx / LD4);
    long j = idx - (long)b * LD4;
    const float4* p = part + (long)b * KS_ * LD4 + j;
    float4 s = p[0];
#pragma unroll
    for (int ks = 1; ks < KS_; ks++) {
        float4 t = p[(long)ks * LD4];
        s.x += t.x; s.y += t.y; s.z += t.z; s.w += t.w;
    }
    out[idx] = s;
}

// ======================= helper kernels =====================================
__global__ __launch_bounds__(256)
void split_arr(const float4* __restrict__ s, uint2* __restrict__ hi,
               uint2* __restrict__ lo, int n4)
{
    int i = blockIdx.x * 256 + threadIdx.x;
    if (i >= n4) return;
    float4 v = s[i];
    __nv_bfloat16 h[4], l[4];
    split2(v.x, h[0], l[0]);
    split2(v.y, h[1], l[1]);
    split2(v.z, h[2], l[2]);
    split2(v.w, h[3], l[3]);
    hi[i] = *reinterpret_cast<uint2*>(h);
    lo[i] = *reinterpret_cast<uint2*>(l);
}

__global__ __launch_bounds__(256)
void transpose_split_w(const float* __restrict__ src,
                       __nv_bfloat16* __restrict__ hi, __nv_bfloat16* __restrict__ lo)
{
    __shared__ float t[32][33];
    const int z = blockIdx.z;
    const int e0 = blockIdx.y * 32, d0 = blockIdx.x * 32;
    const int tx = threadIdx.x & 31, ty = threadIdx.x >> 5;
    const float* s = src + (long)z * D_ * D_;
#pragma unroll
    for (int r = 0; r < 32; r += 8)
        t[ty + r][tx] = s[(long)(e0 + ty + r) * D_ + d0 + tx];
    __syncthreads();
    const long base = (long)z * D_ * D_;
#pragma unroll
    for (int r = 0; r < 32; r += 8) {
        float x = t[tx][ty + r];
        __nv_bfloat16 h, l;
        split2(x, h, l);
        long o = base + (long)(d0 + ty + r) * D_ + e0 + tx;
        hi[o] = h; lo[o] = l;
    }
}

__global__ __launch_bounds__(256)
void wo_permute_split(const float* __restrict__ Wo,
                      __nv_bfloat16* __restrict__ hi, __nv_bfloat16* __restrict__ lo)
{
    long idx = (long)blockIdx.x * 256 + threadIdx.x;
    int f = (int)(idx & 511);
    int e = (int)((idx >> 9) & 511);
    int h = (int)(idx >> 18);
    float x = Wo[(long)e * (H_ * D_) + (f >> 6) * 512 + h * 64 + (f & 63)];
    __nv_bfloat16 hb, lb;
    split2(x, hb, lb);
    hi[idx] = hb; lo[idx] = lb;
}

// in-place row softmax (2048 cols, fp32)
__global__ __launch_bounds__(256)
void softmax_rows(float* __restrict__ data)
{
    float* p = data + (long)blockIdx.x * L_;
    const int tid = threadIdx.x;

    float vals[8];
    float vmax = -1e30f;
#pragma unroll
    for (int i = 0; i < 8; i++) { vals[i] = p[tid + i * 256]; vmax = fmaxf(vmax, vals[i]); }
#pragma unroll
    for (int o = 16; o > 0; o >>= 1) vmax = fmaxf(vmax, __shfl_xor_sync(0xFFFFFFFFu, vmax, o));

    __shared__ float smax[8], ssum[8];
    if ((tid & 31) == 0) smax[tid >> 5] = vmax;
    __syncthreads();
    float m = smax[0];
#pragma unroll
    for (int i = 1; i < 8; i++) m = fmaxf(m, smax[i]);

    float sum = 0.f;
#pragma unroll
    for (int i = 0; i < 8; i++) { vals[i] = __expf(vals[i] - m); sum += vals[i]; }
#pragma unroll
    for (int o = 16; o > 0; o >>= 1) sum += __shfl_xor_sync(0xFFFFFFFFu, sum, o);
    if ((tid & 31) == 0) ssum[tid >> 5] = sum;
    __syncthreads();
    float tot = 0.f;
#pragma unroll
    for (int i = 0; i < 8; i++) tot += ssum[i];
    const float inv = 1.f / tot;
#pragma unroll
    for (int i = 0; i < 8; i++) p[tid + i * 256] = vals[i] * inv;
}

// ======================= launch =============================================
extern "C" void kernel_launch(void* const* d_in, const int* in_sizes, int n_in,
                              void* d_out, int out_size)
{
    const float* q  = (const float*)d_in[0];
    const float* k  = (const float*)d_in[1];
    const float* v  = (const float*)d_in[2];
    const float* Wq = (const float*)d_in[3];
    const float* Wk = (const float*)d_in[4];
    const float* Wv = (const float*)d_in[5];
    const float* Wo = (const float*)d_in[6];

    float* out  = (float*)d_out;
    float* attn = out + (long)B_ * L_ * D_;

    cudaFuncSetAttribute(mma_gemm<0>, cudaFuncAttributeMaxDynamicSharedMemorySize, SMEM_T);
    cudaFuncSetAttribute(mma_gemm<1>, cudaFuncAttributeMaxDynamicSharedMemorySize, SMEM_T);
    cudaFuncSetAttribute(out_gemm,    cudaFuncAttributeMaxDynamicSharedMemorySize, SMEM_O);

#define SYM(p, s) cudaGetSymbolAddress((void**)&p, s)
    __nv_bfloat16 *q_hi, *q_lo, *k_hi, *k_lo, *v_hi, *v_lo;
    __nv_bfloat16 *WqT_hi, *WqT_lo, *WkT_hi, *WkT_lo, *WvT_hi, *WvT_lo, *Wop_hi, *Wop_lo;
    __nv_bfloat16 *MT_hi, *MT_lo, *P_hi, *P_lo;
    __nv_bfloat16 *t_hi, *t_lo, *ZT_hi, *ZT_lo;
    float *part;
    SYM(q_hi, g_q_hi);  SYM(q_lo, g_q_lo);
    SYM(k_hi, g_k_hi);  SYM(k_lo, g_k_lo);
    SYM(v_hi, g_v_hi);  SYM(v_lo, g_v_lo);
    SYM(WqT_hi, g_WqT_hi); SYM(WqT_lo, g_WqT_lo);
    SYM(WkT_hi, g_WkT_hi); SYM(WkT_lo, g_WkT_lo);
    SYM(WvT_hi, g_WvT_hi); SYM(WvT_lo, g_WvT_lo);
    SYM(Wop_hi, g_Wop_hi); SYM(Wop_lo, g_Wop_lo);
    SYM(MT_hi, g_MT_hi);   SYM(MT_lo, g_MT_lo);
    SYM(P_hi, g_P_hi);     SYM(P_lo, g_P_lo);
    SYM(t_hi, g_t_hi);     SYM(t_lo, g_t_lo);
    SYM(ZT_hi, g_ZT_hi);   SYM(ZT_lo, g_ZT_lo);
    SYM(part, g_part);
#undef SYM

    const long sLD = (long)L_ * D_;
    const long sLL = (long)L_ * L_;
    const long sDD = (long)D_ * D_;
    const float inv_sqrt_d = 1.0f / sqrtf((float)D_);

    dim3 blk(256);
    const int n4_in = (B_ * L_ * D_) / 4;

    split_arr<<<(n4_in + 255) / 256, blk>>>((const float4*)q, (uint2*)q_hi, (uint2*)q_lo, n4_in);
    split_arr<<<(n4_in + 255) / 256, blk>>>((const float4*)k, (uint2*)k_hi, (uint2*)k_lo, n4_in);
    split_arr<<<(n4_in + 255) / 256, blk>>>((const float4*)v, (uint2*)v_hi, (uint2*)v_lo, n4_in);
    dim3 gtw(D_ / 32, D_ / 32, H_);
    transpose_split_w<<<gtw, blk>>>(Wq, WqT_hi, WqT_lo);
    transpose_split_w<<<gtw, blk>>>(Wk, WkT_hi, WkT_lo);
    transpose_split_w<<<gtw, blk>>>(Wv, WvT_hi, WvT_lo);
    wo_permute_split<<<(H_ * D_ * D_) / 256, blk>>>(Wo, Wop_hi, Wop_lo);

    // MT[h] = WkT[h] @ WqT[h]^T
    dim3 gW(D_ / 128, D_ / 128, H_);
    mma_gemm<1><<<gW, blk, SMEM_T>>>(WkT_hi, WkT_lo, WqT_hi, WqT_lo,
        nullptr, MT_hi, MT_lo, D_, D_, sDD, sDD, 1, H_, 1, H_, 1, sDD, 1, 0, 1.0f);

    // P[h] = Wo'[h] @ WvT[h]^T
    mma_gemm<1><<<gW, blk, SMEM_T>>>(Wop_hi, Wop_lo, WvT_hi, WvT_lo,
        nullptr, P_hi, P_lo, D_, D_, sDD, sDD, 1, H_, 1, H_, 1, sDD, 1, 0, 1.0f);

    // t[b,h] = q[b] @ MT[h]^T
    dim3 gt(D_ / 128, L_ / 128, B_ * H_);
    mma_gemm<1><<<gt, blk, SMEM_T>>>(q_hi, q_lo, MT_hi, MT_lo,
        nullptr, t_hi, t_lo, D_, D_, sLD, sDD, H_, B_, 1, H_, 1, sLD, 1, 0, 1.0f);

    // scores[b,h] = t[b,h] @ k[b]^T / sqrt(D) -> attn fp32
    dim3 gsc(L_ / 128, L_ / 128, B_ * H_);
    mma_gemm<0><<<gsc, blk, SMEM_T>>>(t_hi, t_lo, k_hi, k_lo,
        attn, nullptr, nullptr, D_, L_, sLD, sLD, 1, B_ * H_, H_, B_, 1, sLL, 1, 0, inv_sqrt_d);

    // ZT[b, e, h*L+m] = P[h] @ v[b]^T
    dim3 gz(L_ / 128, D_ / 128, B_ * H_);
    mma_gemm<1><<<gz, blk, SMEM_T>>>(P_hi, P_lo, v_hi, v_lo,
        nullptr, ZT_hi, ZT_lo, D_, H_ * L_, sDD, sLD, 1, H_, H_, B_,
        H_, (long)D_ * H_ * L_, H_, (long)L_, 1.0f);

    // softmax in place (fp32 only)
    softmax_rows<<<B_ * H_ * L_, blk>>>(attn);

    // out partials: split-K over H*L
    dim3 go(D_ / 128, L_ / 128, B_ * KS_);
    out_gemm<<<go, blk, SMEM_O>>>(attn, ZT_hi, ZT_lo, part);

    // reduce partials -> out
    reduce_part<<<(B_ * L_ * D_ / 4) / 256, blk>>>((const float4*)part, (float4*)out);
}

// round 6
// speedup vs baseline: 1.3120x; 1.3120x over previous
#include <cuda_runtime.h>
#include <cuda_bf16.h>
#include <stdint.h>
#include <math.h>

#define B_  2
#define L_  2048
#define D_  512
#define H_  8
#define HD_ 64

// ======================= scratch (device globals) ==========================
__device__ __nv_bfloat16 g_q_hi [(size_t)B_*L_*D_];
__device__ __nv_bfloat16 g_q_lo [(size_t)B_*L_*D_];
__device__ __nv_bfloat16 g_k_hi [(size_t)B_*L_*D_];
__device__ __nv_bfloat16 g_k_lo [(size_t)B_*L_*D_];
__device__ __nv_bfloat16 g_v_hi [(size_t)B_*L_*D_];
__device__ __nv_bfloat16 g_v_lo [(size_t)B_*L_*D_];
__device__ __nv_bfloat16 g_WqT_hi[(size_t)H_*D_*D_];
__device__ __nv_bfloat16 g_WqT_lo[(size_t)H_*D_*D_];
__device__ __nv_bfloat16 g_WkT_hi[(size_t)H_*D_*D_];
__device__ __nv_bfloat16 g_WkT_lo[(size_t)H_*D_*D_];
__device__ __nv_bfloat16 g_WvT_hi[(size_t)H_*D_*D_];
__device__ __nv_bfloat16 g_WvT_lo[(size_t)H_*D_*D_];
__device__ __nv_bfloat16 g_Wop_hi[(size_t)H_*D_*D_];
__device__ __nv_bfloat16 g_Wop_lo[(size_t)H_*D_*D_];
__device__ __nv_bfloat16 g_MT_hi[(size_t)H_*D_*D_];
__device__ __nv_bfloat16 g_MT_lo[(size_t)H_*D_*D_];
__device__ __nv_bfloat16 g_P_hi [(size_t)H_*D_*D_];
__device__ __nv_bfloat16 g_P_lo [(size_t)H_*D_*D_];
__device__ __nv_bfloat16 g_t_hi [(size_t)B_*H_*L_*D_];
__device__ __nv_bfloat16 g_t_lo [(size_t)B_*H_*L_*D_];
__device__ __nv_bfloat16 g_ZT_hi[(size_t)B_*D_*H_*L_];
__device__ __nv_bfloat16 g_ZT_lo[(size_t)B_*D_*H_*L_];
__device__ __nv_bfloat16 g_at_hi[(size_t)B_*L_*H_*L_];
__device__ __nv_bfloat16 g_at_lo[(size_t)B_*L_*H_*L_];

// ======================= small helpers ======================================
__device__ __forceinline__ uint32_t smem_u32(const void* p) {
    uint32_t a;
    asm("{ .reg .u64 t; cvta.to.shared.u64 t, %1; cvt.u32.u64 %0, t; }"
        : "=r"(a) : "l"(p));
    return a;
}
// SW128 swizzle for 128-byte rows
__device__ __forceinline__ uint32_t swz128(uint32_t o) { return o ^ ((o >> 3) & 0x70); }

__device__ __forceinline__ void cp16(uint32_t s, const void* g) {
    asm volatile("cp.async.cg.shared.global [%0], [%1], 16;" :: "r"(s), "l"(g));
}
#define CP_COMMIT() asm volatile("cp.async.commit_group;" ::: "memory")

__device__ __forceinline__ void ldm4(uint32_t* r, uint32_t a) {
    asm volatile("ldmatrix.sync.aligned.m8n8.x4.shared.b16 {%0,%1,%2,%3}, [%4];"
                 : "=r"(r[0]), "=r"(r[1]), "=r"(r[2]), "=r"(r[3]) : "r"(a));
}
__device__ __forceinline__ void mma_bf16(float* c, const uint32_t* a, const uint32_t* b) {
    asm volatile("mma.sync.aligned.m16n8k16.row.col.f32.bf16.bf16.f32 "
                 "{%0,%1,%2,%3}, {%4,%5,%6,%7}, {%8,%9}, {%0,%1,%2,%3};"
                 : "+f"(c[0]), "+f"(c[1]), "+f"(c[2]), "+f"(c[3])
                 : "r"(a[0]), "r"(a[1]), "r"(a[2]), "r"(a[3]), "r"(b[0]), "r"(b[1]));
}
__device__ __forceinline__ void split2(float x, __nv_bfloat16& h, __nv_bfloat16& l) {
    h = __float2bfloat16(x);
    l = __float2bfloat16(x - __bfloat162float(h));
}
__device__ __forceinline__ void split_pack(float2 v, uint32_t& hi, uint32_t& lo) {
    __nv_bfloat16 h0, l0, h1, l1;
    split2(v.x, h0, l0);
    split2(v.y, h1, l1);
    hi = ((uint32_t)__bfloat16_as_ushort(h1) << 16) | __bfloat16_as_ushort(h0);
    lo = ((uint32_t)__bfloat16_as_ushort(l1) << 16) | __bfloat16_as_ushort(l0);
}

// ======================= bf16x3 HMMA GEMM (KC=64, 3-stage) ==================
// C[m,n] = alpha * sum_k A[m,k]*B[n,k]   (NT, both K-major bf16 hi/lo)
// Batch z: Ab = A + ((z/adiv)%amod)*sA ; Bb = B + ((z/bdiv)%bmod)*sB
// C offset: coff = (z/czdiv)*sC1 + (z%czmod)*sC2 ; C row stride = ldc
#define KC       64
#define TILE_B   (128 * 128)          // 128 rows x 128B (64 bf16) = 16 KB
#define STAGE_B  (4 * TILE_B)         // Ah, Al, Bh, Bl = 64 KB
#define NSTAGE   3
#define SMEM_T   (NSTAGE * STAGE_B)   // 192 KB

template <int MODE>   // 0: fp32 out, 1: bf16 hi/lo out
__global__ __launch_bounds__(256, 1)
void mma_gemm(const __nv_bfloat16* __restrict__ Ahi, const __nv_bfloat16* __restrict__ Alo,
              const __nv_bfloat16* __restrict__ Bhi, const __nv_bfloat16* __restrict__ Blo,
              float* __restrict__ C, __nv_bfloat16* __restrict__ Chi,
              __nv_bfloat16* __restrict__ Clo,
              int K, int ldc, long sA, long sB,
              int adiv, int amod, int bdiv, int bmod,
              int czdiv, long sC1, int czmod, long sC2, float alpha)
{
    extern __shared__ char smem[];
    const uint32_t sb = smem_u32(smem);
    const int tid  = threadIdx.x;
    const int lane = tid & 31, wid = tid >> 5;
    const int moff = (wid & 1) * 64;
    const int noff = (wid >> 1) * 32;

    const int z = blockIdx.z;
    const __nv_bfloat16* A0h = Ahi + (long)((z / adiv) % amod) * sA;
    const __nv_bfloat16* A0l = Alo + (long)((z / adiv) % amod) * sA;
    const __nv_bfloat16* B0h = Bhi + (long)((z / bdiv) % bmod) * sB;
    const __nv_bfloat16* B0l = Blo + (long)((z / bdiv) % bmod) * sB;
    const long coff = (long)(z / czdiv) * sC1 + (long)(z % czmod) * sC2;
    const long m0 = (long)blockIdx.y * 128;
    const long n0 = (long)blockIdx.x * 128;

    float acc[4][4][4];
#pragma unroll
    for (int a = 0; a < 4; a++)
#pragma unroll
        for (int b = 0; b < 4; b++)
#pragma unroll
            for (int c = 0; c < 4; c++) acc[a][b][c] = 0.f;

    const int NC = K / KC;

    // tile fill: 1024 16B-chunks per tile, 256 threads x 4 iterations
#define LOAD_STAGE(cidx) do {                                                    \
        const uint32_t st = sb + ((cidx) % NSTAGE) * STAGE_B;                    \
        const int k0 = (cidx) * KC;                                              \
        _Pragma("unroll")                                                        \
        for (int it = 0; it < 4; it++) {                                         \
            const int idx = tid + it * 256;                                      \
            const int row = idx >> 3, ch = idx & 7;                              \
            const uint32_t so = swz128(row * 128 + ch * 16);                     \
            const long goA = (m0 + row) * (long)K + k0 + ch * 8;                 \
            const long goB = (n0 + row) * (long)K + k0 + ch * 8;                 \
            cp16(st + so,              A0h + goA);                               \
            cp16(st + TILE_B + so,     A0l + goA);                               \
            cp16(st + 2 * TILE_B + so, B0h + goB);                               \
            cp16(st + 3 * TILE_B + so, B0l + goB);                               \
        }                                                                        \
    } while (0)

    LOAD_STAGE(0);
    CP_COMMIT();
    if (NC > 1) LOAD_STAGE(1);
    CP_COMMIT();

    const int arow = (lane & 7) + ((lane >> 3) & 1) * 8;
    const int ach  = (lane >> 4);
    const int brow = (lane & 7) + ((lane >> 4) & 1) * 8;
    const int bch  = ((lane >> 3) & 1);

    for (int c = 0; c < NC; c++) {
        asm volatile("cp.async.wait_group 1;" ::: "memory");
        __syncthreads();
        if (c + 2 < NC) LOAD_STAGE(c + 2);
        CP_COMMIT();

        const uint32_t st = sb + (c % NSTAGE) * STAGE_B;
#pragma unroll
        for (int kk = 0; kk < 4; kk++) {
            uint32_t ah[4][4], al[4][4], bh[4][2], bl[4][2];
#pragma unroll
            for (int mf = 0; mf < 4; mf++) {
                uint32_t ad = st + swz128((moff + mf * 16 + arow) * 128 + (kk * 2 + ach) * 16);
                ldm4(ah[mf], ad);
                ldm4(al[mf], ad + TILE_B);
            }
#pragma unroll
            for (int p = 0; p < 2; p++) {
                uint32_t bd = st + 2 * TILE_B +
                              swz128((noff + p * 16 + brow) * 128 + (kk * 2 + bch) * 16);
                uint32_t r[4];
                ldm4(r, bd);
                bh[2 * p][0] = r[0]; bh[2 * p][1] = r[1];
                bh[2 * p + 1][0] = r[2]; bh[2 * p + 1][1] = r[3];
                ldm4(r, bd + TILE_B);
                bl[2 * p][0] = r[0]; bl[2 * p][1] = r[1];
                bl[2 * p + 1][0] = r[2]; bl[2 * p + 1][1] = r[3];
            }
#pragma unroll
            for (int mf = 0; mf < 4; mf++)
#pragma unroll
                for (int nf = 0; nf < 4; nf++) {
                    mma_bf16(acc[mf][nf], ah[mf], bh[nf]);
                    mma_bf16(acc[mf][nf], ah[mf], bl[nf]);
                    mma_bf16(acc[mf][nf], al[mf], bh[nf]);
                }
        }
    }
#undef LOAD_STAGE

    // ---- epilogue ----
    const int gq = lane >> 2, tg = lane & 3;
#pragma unroll
    for (int mf = 0; mf < 4; mf++)
#pragma unroll
        for (int nf = 0; nf < 4; nf++) {
            const long row = m0 + moff + mf * 16 + gq;
            const long col = n0 + noff + nf * 8 + tg * 2;
            float v0 = alpha * acc[mf][nf][0];
            float v1 = alpha * acc[mf][nf][1];
            float v2 = alpha * acc[mf][nf][2];
            float v3 = alpha * acc[mf][nf][3];
            if (MODE == 0) {
                float2 p0 = {v0, v1}, p1 = {v2, v3};
                *reinterpret_cast<float2*>(C + coff + row * ldc + col)       = p0;
                *reinterpret_cast<float2*>(C + coff + (row + 8) * ldc + col) = p1;
            } else {
                uint32_t hp0, lp0, hp1, lp1;
                split_pack({v0, v1}, hp0, lp0);
                split_pack({v2, v3}, hp1, lp1);
                *reinterpret_cast<uint32_t*>(Chi + coff + row * ldc + col)       = hp0;
                *reinterpret_cast<uint32_t*>(Clo + coff + row * ldc + col)       = lp0;
                *reinterpret_cast<uint32_t*>(Chi + coff + (row + 8) * ldc + col) = hp1;
                *reinterpret_cast<uint32_t*>(Clo + coff + (row + 8) * ldc + col) = lp1;
            }
        }
}

// ======================= helper kernels =====================================
__global__ __launch_bounds__(256)
void split_arr(const float4* __restrict__ s, uint2* __restrict__ hi,
               uint2* __restrict__ lo, int n4)
{
    int i = blockIdx.x * 256 + threadIdx.x;
    if (i >= n4) return;
    float4 v = s[i];
    __nv_bfloat16 h[4], l[4];
    split2(v.x, h[0], l[0]);
    split2(v.y, h[1], l[1]);
    split2(v.z, h[2], l[2]);
    split2(v.w, h[3], l[3]);
    hi[i] = *reinterpret_cast<uint2*>(h);
    lo[i] = *reinterpret_cast<uint2*>(l);
}

// W [Z,512,512] fp32 -> WT hi/lo [Z,512,512] with per-z transpose
__global__ __launch_bounds__(256)
void transpose_split_w(const float* __restrict__ src,
                       __nv_bfloat16* __restrict__ hi, __nv_bfloat16* __restrict__ lo)
{
    __shared__ float t[32][33];
    const int z = blockIdx.z;
    const int e0 = blockIdx.y * 32, d0 = blockIdx.x * 32;
    const int tx = threadIdx.x & 31, ty = threadIdx.x >> 5;
    const float* s = src + (long)z * D_ * D_;
#pragma unroll
    for (int r = 0; r < 32; r += 8)
        t[ty + r][tx] = s[(long)(e0 + ty + r) * D_ + d0 + tx];
    __syncthreads();
    const long base = (long)z * D_ * D_;
#pragma unroll
    for (int r = 0; r < 32; r += 8) {
        float x = t[tx][ty + r];
        __nv_bfloat16 h, l;
        split2(x, h, l);
        long o = base + (long)(d0 + ty + r) * D_ + e0 + tx;
        hi[o] = h; lo[o] = l;
    }
}

// Wo [D, H*D] -> Wo'[h][e,f] = Wo[e, (f/64)*512 + h*64 + (f%64)], split hi/lo
__global__ __launch_bounds__(256)
void wo_permute_split(const float* __restrict__ Wo,
                      __nv_bfloat16* __restrict__ hi, __nv_bfloat16* __restrict__ lo)
{
    long idx = (long)blockIdx.x * 256 + threadIdx.x;
    int f = (int)(idx & 511);
    int e = (int)((idx >> 9) & 511);
    int h = (int)(idx >> 18);
    float x = Wo[(long)e * (H_ * D_) + (f >> 6) * 512 + h * 64 + (f & 63)];
    __nv_bfloat16 hb, lb;
    split2(x, hb, lb);
    hi[idx] = hb; lo[idx] = lb;
}

// softmax over rows of 2048 in place (fp32, [b,h,l,m]) + bf16 hi/lo in [b,l,h,m]
__global__ __launch_bounds__(256)
void softmax_split(float* __restrict__ data,
                   __nv_bfloat16* __restrict__ hi, __nv_bfloat16* __restrict__ lo)
{
    const int r = blockIdx.x;                 // (b*H + h)*L + l
    const int b = r >> 14;
    const int h = (r >> 11) & (H_ - 1);
    const int l = r & (L_ - 1);
    float* p = data + (long)r * L_;
    const long ob = (((long)b * L_ + l) * H_ + h) * L_;
    const int tid = threadIdx.x;

    float vals[8];
    float vmax = -1e30f;
#pragma unroll
    for (int i = 0; i < 8; i++) { vals[i] = p[tid + i * 256]; vmax = fmaxf(vmax, vals[i]); }
#pragma unroll
    for (int o = 16; o > 0; o >>= 1) vmax = fmaxf(vmax, __shfl_xor_sync(0xFFFFFFFFu, vmax, o));

    __shared__ float smax[8], ssum[8];
    if ((tid & 31) == 0) smax[tid >> 5] = vmax;
    __syncthreads();
    float m = smax[0];
#pragma unroll
    for (int i = 1; i < 8; i++) m = fmaxf(m, smax[i]);

    float sum = 0.f;
#pragma unroll
    for (int i = 0; i < 8; i++) { vals[i] = __expf(vals[i] - m); sum += vals[i]; }
#pragma unroll
    for (int o = 16; o > 0; o >>= 1) sum += __shfl_xor_sync(0xFFFFFFFFu, sum, o);
    if ((tid & 31) == 0) ssum[tid >> 5] = sum;
    __syncthreads();
    float tot = 0.f;
#pragma unroll
    for (int i = 0; i < 8; i++) tot += ssum[i];
    const float inv = 1.f / tot;
#pragma unroll
    for (int i = 0; i < 8; i++) {
        float y = vals[i] * inv;
        p[tid + i * 256] = y;
        __nv_bfloat16 hh, ll;
        split2(y, hh, ll);
        hi[ob + tid + i * 256] = hh;
        lo[ob + tid + i * 256] = ll;
    }
}

// ======================= launch =============================================
extern "C" void kernel_launch(void* const* d_in, const int* in_sizes, int n_in,
                              void* d_out, int out_size)
{
    const float* q  = (const float*)d_in[0];
    const float* k  = (const float*)d_in[1];
    const float* v  = (const float*)d_in[2];
    const float* Wq = (const float*)d_in[3];
    const float* Wk = (const float*)d_in[4];
    const float* Wv = (const float*)d_in[5];
    const float* Wo = (const float*)d_in[6];

    float* out  = (float*)d_out;
    float* attn = out + (long)B_ * L_ * D_;

    cudaFuncSetAttribute(mma_gemm<0>, cudaFuncAttributeMaxDynamicSharedMemorySize, SMEM_T);
    cudaFuncSetAttribute(mma_gemm<1>, cudaFuncAttributeMaxDynamicSharedMemorySize, SMEM_T);

#define SYM(p, s) cudaGetSymbolAddress((void**)&p, s)
    __nv_bfloat16 *q_hi, *q_lo, *k_hi, *k_lo, *v_hi, *v_lo;
    __nv_bfloat16 *WqT_hi, *WqT_lo, *WkT_hi, *WkT_lo, *WvT_hi, *WvT_lo, *Wop_hi, *Wop_lo;
    __nv_bfloat16 *MT_hi, *MT_lo, *P_hi, *P_lo;
    __nv_bfloat16 *t_hi, *t_lo, *ZT_hi, *ZT_lo, *at_hi, *at_lo;
    SYM(q_hi, g_q_hi);  SYM(q_lo, g_q_lo);
    SYM(k_hi, g_k_hi);  SYM(k_lo, g_k_lo);
    SYM(v_hi, g_v_hi);  SYM(v_lo, g_v_lo);
    SYM(WqT_hi, g_WqT_hi); SYM(WqT_lo, g_WqT_lo);
    SYM(WkT_hi, g_WkT_hi); SYM(WkT_lo, g_WkT_lo);
    SYM(WvT_hi, g_WvT_hi); SYM(WvT_lo, g_WvT_lo);
    SYM(Wop_hi, g_Wop_hi); SYM(Wop_lo, g_Wop_lo);
    SYM(MT_hi, g_MT_hi);   SYM(MT_lo, g_MT_lo);
    SYM(P_hi, g_P_hi);     SYM(P_lo, g_P_lo);
    SYM(t_hi, g_t_hi);     SYM(t_lo, g_t_lo);
    SYM(ZT_hi, g_ZT_hi);   SYM(ZT_lo, g_ZT_lo);
    SYM(at_hi, g_at_hi);   SYM(at_lo, g_at_lo);
#undef SYM

    const long sLD = (long)L_ * D_;
    const long sLL = (long)L_ * L_;
    const long sDD = (long)D_ * D_;
    const float inv_sqrt_d = 1.0f / sqrtf((float)D_);

    dim3 blk(256);
    const int n4_in = (B_ * L_ * D_) / 4;

    // 0) split q,k,v; transpose-split Wq,Wk,Wv; permute-split Wo
    split_arr<<<(n4_in + 255) / 256, blk>>>((const float4*)q, (uint2*)q_hi, (uint2*)q_lo, n4_in);
    split_arr<<<(n4_in + 255) / 256, blk>>>((const float4*)k, (uint2*)k_hi, (uint2*)k_lo, n4_in);
    split_arr<<<(n4_in + 255) / 256, blk>>>((const float4*)v, (uint2*)v_hi, (uint2*)v_lo, n4_in);
    dim3 gtw(D_ / 32, D_ / 32, H_);
    transpose_split_w<<<gtw, blk>>>(Wq, WqT_hi, WqT_lo);
    transpose_split_w<<<gtw, blk>>>(Wk, WkT_hi, WkT_lo);
    transpose_split_w<<<gtw, blk>>>(Wv, WvT_hi, WvT_lo);
    wo_permute_split<<<(H_ * D_ * D_) / 256, blk>>>(Wo, Wop_hi, Wop_lo);

    // 1) MT[h] = WkT[h] @ WqT[h]^T
    dim3 gW(D_ / 128, D_ / 128, H_);
    mma_gemm<1><<<gW, blk, SMEM_T>>>(WkT_hi, WkT_lo, WqT_hi, WqT_lo,
        nullptr, MT_hi, MT_lo, D_, D_, sDD, sDD, 1, H_, 1, H_, 1, sDD, 1, 0, 1.0f);

    // 2) P[h] = Wo'[h] @ WvT[h]^T
    mma_gemm<1><<<gW, blk, SMEM_T>>>(Wop_hi, Wop_lo, WvT_hi, WvT_lo,
        nullptr, P_hi, P_lo, D_, D_, sDD, sDD, 1, H_, 1, H_, 1, sDD, 1, 0, 1.0f);

    // 3) t[b,h] = q[b] @ MT[h]^T
    dim3 gt(D_ / 128, L_ / 128, B_ * H_);
    mma_gemm<1><<<gt, blk, SMEM_T>>>(q_hi, q_lo, MT_hi, MT_lo,
        nullptr, t_hi, t_lo, D_, D_, sLD, sDD, H_, B_, 1, H_, 1, sLD, 1, 0, 1.0f);

    // 4) scores[b,h] = t[b,h] @ k[b]^T / sqrt(D) -> attn fp32 in d_out
    dim3 gsc(L_ / 128, L_ / 128, B_ * H_);
    mma_gemm<0><<<gsc, blk, SMEM_T>>>(t_hi, t_lo, k_hi, k_lo,
        attn, nullptr, nullptr, D_, L_, sLD, sLD, 1, B_ * H_, H_, B_, 1, sLL, 1, 0, inv_sqrt_d);

    // 5) ZT[b, e, h*L+m] = P[h] @ v[b]^T
    dim3 gz(L_ / 128, D_ / 128, B_ * H_);
    mma_gemm<1><<<gz, blk, SMEM_T>>>(P_hi, P_lo, v_hi, v_lo,
        nullptr, ZT_hi, ZT_lo, D_, H_ * L_, sDD, sLD, 1, H_, H_, B_,
        H_, (long)D_ * H_ * L_, H_, (long)L_, 1.0f);

    // 6) softmax in place + bf16 hi/lo in permuted [b,l,h,m] layout
    softmax_split<<<B_ * H_ * L_, blk>>>(attn, at_hi, at_lo);

    // 7) out[b] = at'[b] [L, H*L] @ ZT'[b] [D, H*L]^T  (K = H*L)
    dim3 go(D_ / 128, L_ / 128, B_);
    mma_gemm<0><<<go, blk, SMEM_T>>>(at_hi, at_lo, ZT_hi, ZT_lo,
        out, nullptr, nullptr, H_ * L_, D_, (long)L_ * H_ * L_, (long)D_ * H_ * L_,
        1, B_, 1, B_, 1, sLD, 1, 0, 1.0f);
}

// round 7
// speedup vs baseline: 1.4555x; 1.1094x over previous
#include <cuda_runtime.h>
#include <cuda_bf16.h>
#include <stdint.h>
#include <math.h>

#define B_  2
#define L_  2048
#define D_  512
#define H_  8
#define HD_ 64
#define KS_ 8

// ======================= scratch (device globals) ==========================
__device__ __nv_bfloat16 g_q_hi [(size_t)B_*L_*D_];
__device__ __nv_bfloat16 g_q_lo [(size_t)B_*L_*D_];
__device__ __nv_bfloat16 g_k_hi [(size_t)B_*L_*D_];
__device__ __nv_bfloat16 g_k_lo [(size_t)B_*L_*D_];
__device__ __nv_bfloat16 g_v_hi [(size_t)B_*L_*D_];
__device__ __nv_bfloat16 g_v_lo [(size_t)B_*L_*D_];
__device__ __nv_bfloat16 g_WqT_hi[(size_t)H_*D_*D_];
__device__ __nv_bfloat16 g_WqT_lo[(size_t)H_*D_*D_];
__device__ __nv_bfloat16 g_WkT_hi[(size_t)H_*D_*D_];
__device__ __nv_bfloat16 g_WkT_lo[(size_t)H_*D_*D_];
__device__ __nv_bfloat16 g_WvT_hi[(size_t)H_*D_*D_];
__device__ __nv_bfloat16 g_WvT_lo[(size_t)H_*D_*D_];
__device__ __nv_bfloat16 g_Wop_hi[(size_t)H_*D_*D_];
__device__ __nv_bfloat16 g_Wop_lo[(size_t)H_*D_*D_];
__device__ __nv_bfloat16 g_MT_hi[(size_t)H_*D_*D_];
__device__ __nv_bfloat16 g_MT_lo[(size_t)H_*D_*D_];
__device__ __nv_bfloat16 g_P_hi [(size_t)H_*D_*D_];
__device__ __nv_bfloat16 g_P_lo [(size_t)H_*D_*D_];
__device__ __nv_bfloat16 g_t_hi [(size_t)B_*H_*L_*D_];
__device__ __nv_bfloat16 g_t_lo [(size_t)B_*H_*L_*D_];
__device__ __nv_bfloat16 g_ZT_hi[(size_t)B_*D_*H_*L_];
__device__ __nv_bfloat16 g_ZT_lo[(size_t)B_*D_*H_*L_];
__device__ __nv_bfloat16 g_at_hi[(size_t)B_*L_*H_*L_];
__device__ __nv_bfloat16 g_at_lo[(size_t)B_*L_*H_*L_];
__device__ float         g_part [(size_t)B_*KS_*L_*D_];

// ======================= small helpers ======================================
__device__ __forceinline__ uint32_t smem_u32(const void* p) {
    uint32_t a;
    asm("{ .reg .u64 t; cvta.to.shared.u64 t, %1; cvt.u32.u64 %0, t; }"
        : "=r"(a) : "l"(p));
    return a;
}
__device__ __forceinline__ uint32_t swz128(uint32_t o) { return o ^ ((o >> 3) & 0x70); }

__device__ __forceinline__ void cp16(uint32_t s, const void* g) {
    asm volatile("cp.async.cg.shared.global [%0], [%1], 16;" :: "r"(s), "l"(g));
}
#define CP_COMMIT() asm volatile("cp.async.commit_group;" ::: "memory")

__device__ __forceinline__ void ldm4(uint32_t* r, uint32_t a) {
    asm volatile("ldmatrix.sync.aligned.m8n8.x4.shared.b16 {%0,%1,%2,%3}, [%4];"
                 : "=r"(r[0]), "=r"(r[1]), "=r"(r[2]), "=r"(r[3]) : "r"(a));
}
__device__ __forceinline__ void mma_bf16(float* c, const uint32_t* a, const uint32_t* b) {
    asm volatile("mma.sync.aligned.m16n8k16.row.col.f32.bf16.bf16.f32 "
                 "{%0,%1,%2,%3}, {%4,%5,%6,%7}, {%8,%9}, {%0,%1,%2,%3};"
                 : "+f"(c[0]), "+f"(c[1]), "+f"(c[2]), "+f"(c[3])
                 : "r"(a[0]), "r"(a[1]), "r"(a[2]), "r"(a[3]), "r"(b[0]), "r"(b[1]));
}
__device__ __forceinline__ void split2(float x, __nv_bfloat16& h, __nv_bfloat16& l) {
    h = __float2bfloat16(x);
    l = __float2bfloat16(x - __bfloat162float(h));
}
__device__ __forceinline__ void split_pack(float2 v, uint32_t& hi, uint32_t& lo) {
    __nv_bfloat16 h0, l0, h1, l1;
    split2(v.x, h0, l0);
    split2(v.y, h1, l1);
    hi = ((uint32_t)__bfloat16_as_ushort(h1) << 16) | __bfloat16_as_ushort(h0);
    lo = ((uint32_t)__bfloat16_as_ushort(l1) << 16) | __bfloat16_as_ushort(l0);
}

// =============== persistent bf16x3 HMMA GEMM (KC=64, 3-stage) ===============
// C[m,n] = alpha * sum_k A[m,k]*B[n,k]  (NT; A rows stride lda, B rows stride ldb)
// Tile t -> (z, ty, tx):  z = t/(gx*gy), ty = (t%(gx*gy))/gx, tx = t%gx
// A offset: ((z/adiv)%amod)*sA + (z%azmod)*sA2 + ty*128*lda
// B offset: ((z/bdiv)%bmod)*sB + (z%azmod)*sB2 + tx*128*ldb
// C offset: (z/czdiv)*sC1 + (z%czmod)*sC2 + ty*128*ldc + tx*128
#define KC       64
#define TILE_B   (128 * 128)
#define STAGE_B  (4 * TILE_B)
#define NSTAGE   3
#define SMEM_T   (NSTAGE * STAGE_B)   // 192 KB

struct TileP {
    const __nv_bfloat16 *ah, *al, *bh, *bl;
    long coff;
};

template <int MODE>   // 0: fp32 out, 1: bf16 hi/lo out
__global__ __launch_bounds__(256, 1)
void mma_gemm(const __nv_bfloat16* __restrict__ Ahi, const __nv_bfloat16* __restrict__ Alo,
              const __nv_bfloat16* __restrict__ Bhi, const __nv_bfloat16* __restrict__ Blo,
              float* __restrict__ C, __nv_bfloat16* __restrict__ Chi,
              __nv_bfloat16* __restrict__ Clo,
              int ntiles, int gx, int gy,
              int K, int lda, int ldb, int ldc,
              long sA, long sB, int adiv, int amod, int bdiv, int bmod,
              int azmod, long sA2, long sB2,
              int czdiv, long sC1, int czmod, long sC2, float alpha)
{
    extern __shared__ char smem[];
    const uint32_t sb = smem_u32(smem);
    const int tid  = threadIdx.x;
    const int lane = tid & 31, wid = tid >> 5;
    const int moff = (wid & 1) * 64;
    const int noff = (wid >> 1) * 32;

    int t0 = blockIdx.x;
    if (t0 >= ntiles) return;

    auto tileinfo = [&](int t) -> TileP {
        const int gxy = gx * gy;
        const int z = t / gxy;
        const int r = t - z * gxy;
        const int ty = r / gx;
        const int tx = r - ty * gx;
        const long aoff = (long)((z / adiv) % amod) * sA + (long)(z % azmod) * sA2
                          + (long)ty * 128 * lda;
        const long boff = (long)((z / bdiv) % bmod) * sB + (long)(z % azmod) * sB2
                          + (long)tx * 128 * ldb;
        TileP p;
        p.ah = Ahi + aoff;  p.al = Alo + aoff;
        p.bh = Bhi + boff;  p.bl = Blo + boff;
        p.coff = (long)(z / czdiv) * sC1 + (long)(z % czmod) * sC2
                 + (long)ty * 128 * ldc + (long)tx * 128;
        return p;
    };

#define LOADT(T, cidx, stg) do {                                                 \
        const uint32_t st = sb + (stg) * STAGE_B;                                \
        const int k0 = (cidx) * KC;                                              \
        _Pragma("unroll")                                                        \
        for (int it = 0; it < 4; it++) {                                         \
            const int idx = tid + it * 256;                                      \
            const int row = idx >> 3, ch = idx & 7;                              \
            const uint32_t so = swz128(row * 128 + ch * 16);                     \
            const long goA = (long)row * lda + k0 + ch * 8;                      \
            const long goB = (long)row * ldb + k0 + ch * 8;                      \
            cp16(st + so,              (T).ah + goA);                            \
            cp16(st + TILE_B + so,     (T).al + goA);                            \
            cp16(st + 2 * TILE_B + so, (T).bh + goB);                            \
            cp16(st + 3 * TILE_B + so, (T).bl + goB);                            \
        }                                                                        \
    } while (0)

    const int NC = K / KC;                  // >= 8 for all uses
    const int stride = gridDim.x;

    TileP cur = tileinfo(t0);
    LOADT(cur, 0, 0); CP_COMMIT();
    LOADT(cur, 1, 1); CP_COMMIT();
    int lstage = 2;       // stage for next load
    int cstage = 0;       // stage for next compute

    const int arow = (lane & 7) + ((lane >> 3) & 1) * 8;
    const int ach  = (lane >> 4);
    const int brow = (lane & 7) + ((lane >> 4) & 1) * 8;
    const int bch  = ((lane >> 3) & 1);
    const int gq = lane >> 2, tg = lane & 3;

    for (int t = t0; t < ntiles; t += stride) {
        const int tn = t + stride;
        const bool has_next = tn < ntiles;
        TileP nxt = has_next ? tileinfo(tn) : cur;

        float acc[4][4][4];
#pragma unroll
        for (int a = 0; a < 4; a++)
#pragma unroll
            for (int b = 0; b < 4; b++)
#pragma unroll
                for (int c = 0; c < 4; c++) acc[a][b][c] = 0.f;

        for (int c = 0; c < NC; c++) {
            asm volatile("cp.async.wait_group 1;" ::: "memory");
            __syncthreads();
            const int cc = c + 2;
            if (cc < NC) {
                LOADT(cur, cc, lstage);
            } else if (has_next && cc - NC < 2) {
                LOADT(nxt, cc - NC, lstage);
            }
            CP_COMMIT();
            lstage = (lstage == 2) ? 0 : lstage + 1;

            const uint32_t st = sb + cstage * STAGE_B;
            cstage = (cstage == 2) ? 0 : cstage + 1;
#pragma unroll
            for (int kk = 0; kk < 4; kk++) {
                uint32_t ah[4][4], al[4][4], bh[4][2], bl[4][2];
#pragma unroll
                for (int mf = 0; mf < 4; mf++) {
                    uint32_t ad = st + swz128((moff + mf * 16 + arow) * 128 + (kk * 2 + ach) * 16);
                    ldm4(ah[mf], ad);
                    ldm4(al[mf], ad + TILE_B);
                }
#pragma unroll
                for (int p = 0; p < 2; p++) {
                    uint32_t bd = st + 2 * TILE_B +
                                  swz128((noff + p * 16 + brow) * 128 + (kk * 2 + bch) * 16);
                    uint32_t r[4];
                    ldm4(r, bd);
                    bh[2 * p][0] = r[0]; bh[2 * p][1] = r[1];
                    bh[2 * p + 1][0] = r[2]; bh[2 * p + 1][1] = r[3];
                    ldm4(r, bd + TILE_B);
                    bl[2 * p][0] = r[0]; bl[2 * p][1] = r[1];
                    bl[2 * p + 1][0] = r[2]; bl[2 * p + 1][1] = r[3];
                }
#pragma unroll
                for (int mf = 0; mf < 4; mf++)
#pragma unroll
                    for (int nf = 0; nf < 4; nf++) {
                        mma_bf16(acc[mf][nf], ah[mf], bh[nf]);
                        mma_bf16(acc[mf][nf], ah[mf], bl[nf]);
                        mma_bf16(acc[mf][nf], al[mf], bh[nf]);
                    }
            }
        }

        // ---- epilogue (overlaps next tile's in-flight stage loads) ----
#pragma unroll
        for (int mf = 0; mf < 4; mf++)
#pragma unroll
            for (int nf = 0; nf < 4; nf++) {
                const long row = moff + mf * 16 + gq;
                const long col = noff + nf * 8 + tg * 2;
                float v0 = alpha * acc[mf][nf][0];
                float v1 = alpha * acc[mf][nf][1];
                float v2 = alpha * acc[mf][nf][2];
                float v3 = alpha * acc[mf][nf][3];
                if (MODE == 0) {
                    float2 p0 = {v0, v1}, p1 = {v2, v3};
                    *reinterpret_cast<float2*>(C + cur.coff + row * ldc + col)       = p0;
                    *reinterpret_cast<float2*>(C + cur.coff + (row + 8) * ldc + col) = p1;
                } else {
                    uint32_t hp0, lp0, hp1, lp1;
                    split_pack({v0, v1}, hp0, lp0);
                    split_pack({v2, v3}, hp1, lp1);
                    *reinterpret_cast<uint32_t*>(Chi + cur.coff + row * ldc + col)       = hp0;
                    *reinterpret_cast<uint32_t*>(Clo + cur.coff + row * ldc + col)       = lp0;
                    *reinterpret_cast<uint32_t*>(Chi + cur.coff + (row + 8) * ldc + col) = hp1;
                    *reinterpret_cast<uint32_t*>(Clo + cur.coff + (row + 8) * ldc + col) = lp1;
                }
            }
        cur = nxt;
    }
#undef LOADT
}

// ======================= helper kernels =====================================
__global__ __launch_bounds__(256)
void split_arr(const float4* __restrict__ s, uint2* __restrict__ hi,
               uint2* __restrict__ lo, int n4)
{
    int i = blockIdx.x * 256 + threadIdx.x;
    if (i >= n4) return;
    float4 v = s[i];
    __nv_bfloat16 h[4], l[4];
    split2(v.x, h[0], l[0]);
    split2(v.y, h[1], l[1]);
    split2(v.z, h[2], l[2]);
    split2(v.w, h[3], l[3]);
    hi[i] = *reinterpret_cast<uint2*>(h);
    lo[i] = *reinterpret_cast<uint2*>(l);
}

__global__ __launch_bounds__(256)
void transpose_split_w(const float* __restrict__ src,
                       __nv_bfloat16* __restrict__ hi, __nv_bfloat16* __restrict__ lo)
{
    __shared__ float t[32][33];
    const int z = blockIdx.z;
    const int e0 = blockIdx.y * 32, d0 = blockIdx.x * 32;
    const int tx = threadIdx.x & 31, ty = threadIdx.x >> 5;
    const float* s = src + (long)z * D_ * D_;
#pragma unroll
    for (int r = 0; r < 32; r += 8)
        t[ty + r][tx] = s[(long)(e0 + ty + r) * D_ + d0 + tx];
    __syncthreads();
    const long base = (long)z * D_ * D_;
#pragma unroll
    for (int r = 0; r < 32; r += 8) {
        float x = t[tx][ty + r];
        __nv_bfloat16 h, l;
        split2(x, h, l);
        long o = base + (long)(d0 + ty + r) * D_ + e0 + tx;
        hi[o] = h; lo[o] = l;
    }
}

__global__ __launch_bounds__(256)
void wo_permute_split(const float* __restrict__ Wo,
                      __nv_bfloat16* __restrict__ hi, __nv_bfloat16* __restrict__ lo)
{
    long idx = (long)blockIdx.x * 256 + threadIdx.x;
    int f = (int)(idx & 511);
    int e = (int)((idx >> 9) & 511);
    int h = (int)(idx >> 18);
    float x = Wo[(long)e * (H_ * D_) + (f >> 6) * 512 + h * 64 + (f & 63)];
    __nv_bfloat16 hb, lb;
    split2(x, hb, lb);
    hi[idx] = hb; lo[idx] = lb;
}

// softmax over rows of 2048 in place (fp32, [b,h,l,m]) + bf16 hi/lo in [b,l,h,m]
// pair-packed: thread handles 4 float2 pairs
__global__ __launch_bounds__(256)
void softmax_split(float* __restrict__ data,
                   uint32_t* __restrict__ hi, uint32_t* __restrict__ lo)
{
    const int r = blockIdx.x;
    const int b = r >> 14;
    const int h = (r >> 11) & (H_ - 1);
    const int l = r & (L_ - 1);
    float2* p = reinterpret_cast<float2*>(data + (long)r * L_);
    const long ob2 = ((((long)b * L_ + l) * H_ + h) * L_) >> 1;   // in pairs
    const int tid = threadIdx.x;

    float2 vals[4];
    float vmax = -1e30f;
#pragma unroll
    for (int i = 0; i < 4; i++) {
        vals[i] = p[tid + i * 256];
        vmax = fmaxf(vmax, fmaxf(vals[i].x, vals[i].y));
    }
#pragma unroll
    for (int o = 16; o > 0; o >>= 1) vmax = fmaxf(vmax, __shfl_xor_sync(0xFFFFFFFFu, vmax, o));

    __shared__ float smax[8], ssum[8];
    if ((tid & 31) == 0) smax[tid >> 5] = vmax;
    __syncthreads();
    float m = smax[0];
#pragma unroll
    for (int i = 1; i < 8; i++) m = fmaxf(m, smax[i]);

    float sum = 0.f;
#pragma unroll
    for (int i = 0; i < 4; i++) {
        vals[i].x = __expf(vals[i].x - m);
        vals[i].y = __expf(vals[i].y - m);
        sum += vals[i].x + vals[i].y;
    }
#pragma unroll
    for (int o = 16; o > 0; o >>= 1) sum += __shfl_xor_sync(0xFFFFFFFFu, sum, o);
    if ((tid & 31) == 0) ssum[tid >> 5] = sum;
    __syncthreads();
    float tot = 0.f;
#pragma unroll
    for (int i = 0; i < 8; i++) tot += ssum[i];
    const float inv = 1.f / tot;
#pragma unroll
    for (int i = 0; i < 4; i++) {
        float2 y = {vals[i].x * inv, vals[i].y * inv};
        p[tid + i * 256] = y;
        uint32_t hp, lp;
        split_pack(y, hp, lp);
        hi[ob2 + tid + i * 256] = hp;
        lo[ob2 + tid + i * 256] = lp;
    }
}

// reduce partials: out[b][j] = sum_ks part[b*KS+ks][j]
__global__ __launch_bounds__(256)
void reduce_part(const float4* __restrict__ part, float4* __restrict__ out)
{
    const int LD4 = L_ * D_ / 4;
    long idx = (long)blockIdx.x * 256 + threadIdx.x;
    int b = (int)(idx / LD4);
    long j = idx - (long)b * LD4;
    const float4* p = part + (long)b * KS_ * LD4 + j;
    float4 s = p[0];
#pragma unroll
    for (int ks = 1; ks < KS_; ks++) {
        float4 t = p[(long)ks * LD4];
        s.x += t.x; s.y += t.y; s.z += t.z; s.w += t.w;
    }
    out[idx] = s;
}

// ======================= launch =============================================
extern "C" void kernel_launch(void* const* d_in, const int* in_sizes, int n_in,
                              void* d_out, int out_size)
{
    const float* q  = (const float*)d_in[0];
    const float* k  = (const float*)d_in[1];
    const float* v  = (const float*)d_in[2];
    const float* Wq = (const float*)d_in[3];
    const float* Wk = (const float*)d_in[4];
    const float* Wv = (const float*)d_in[5];
    const float* Wo = (const float*)d_in[6];

    float* out  = (float*)d_out;
    float* attn = out + (long)B_ * L_ * D_;

    static int nsm = 0;
    if (!nsm) {
        cudaDeviceGetAttribute(&nsm, cudaDevAttrMultiProcessorCount, 0);
        cudaFuncSetAttribute(mma_gemm<0>, cudaFuncAttributeMaxDynamicSharedMemorySize, SMEM_T);
        cudaFuncSetAttribute(mma_gemm<1>, cudaFuncAttributeMaxDynamicSharedMemorySize, SMEM_T);
        if (nsm <= 0) nsm = 148;
    }

#define SYM(p, s) cudaGetSymbolAddress((void**)&p, s)
    __nv_bfloat16 *q_hi, *q_lo, *k_hi, *k_lo, *v_hi, *v_lo;
    __nv_bfloat16 *WqT_hi, *WqT_lo, *WkT_hi, *WkT_lo, *WvT_hi, *WvT_lo, *Wop_hi, *Wop_lo;
    __nv_bfloat16 *MT_hi, *MT_lo, *P_hi, *P_lo;
    __nv_bfloat16 *t_hi, *t_lo, *ZT_hi, *ZT_lo, *at_hi, *at_lo;
    float *part;
    SYM(q_hi, g_q_hi);  SYM(q_lo, g_q_lo);
    SYM(k_hi, g_k_hi);  SYM(k_lo, g_k_lo);
    SYM(v_hi, g_v_hi);  SYM(v_lo, g_v_lo);
    SYM(WqT_hi, g_WqT_hi); SYM(WqT_lo, g_WqT_lo);
    SYM(WkT_hi, g_WkT_hi); SYM(WkT_lo, g_WkT_lo);
    SYM(WvT_hi, g_WvT_hi); SYM(WvT_lo, g_WvT_lo);
    SYM(Wop_hi, g_Wop_hi); SYM(Wop_lo, g_Wop_lo);
    SYM(MT_hi, g_MT_hi);   SYM(MT_lo, g_MT_lo);
    SYM(P_hi, g_P_hi);     SYM(P_lo, g_P_lo);
    SYM(t_hi, g_t_hi);     SYM(t_lo, g_t_lo);
    SYM(ZT_hi, g_ZT_hi);   SYM(ZT_lo, g_ZT_lo);
    SYM(at_hi, g_at_hi);   SYM(at_lo, g_at_lo);
    SYM(part, g_part);
#undef SYM

    const long sLD = (long)L_ * D_;
    const long sLL = (long)L_ * L_;
    const long sDD = (long)D_ * D_;
    const float inv_sqrt_d = 1.0f / sqrtf((float)D_);

    dim3 blk(256);
    const int n4_in = (B_ * L_ * D_) / 4;

    // 0) preprocessing splits
    split_arr<<<(n4_in + 255) / 256, blk>>>((const float4*)q, (uint2*)q_hi, (uint2*)q_lo, n4_in);
    split_arr<<<(n4_in + 255) / 256, blk>>>((const float4*)k, (uint2*)k_hi, (uint2*)k_lo, n4_in);
    split_arr<<<(n4_in + 255) / 256, blk>>>((const float4*)v, (uint2*)v_hi, (uint2*)v_lo, n4_in);
    dim3 gtw(D_ / 32, D_ / 32, H_);
    transpose_split_w<<<gtw, blk>>>(Wq, WqT_hi, WqT_lo);
    transpose_split_w<<<gtw, blk>>>(Wk, WkT_hi, WkT_lo);
    transpose_split_w<<<gtw, blk>>>(Wv, WvT_hi, WvT_lo);
    wo_permute_split<<<(H_ * D_ * D_) / 256, blk>>>(Wo, Wop_hi, Wop_lo);

    // 1) MT[h] = WkT[h] @ WqT[h]^T   (ntiles = 4*4*8 = 128)
    mma_gemm<1><<<nsm, blk, SMEM_T>>>(WkT_hi, WkT_lo, WqT_hi, WqT_lo,
        nullptr, MT_hi, MT_lo,
        128, 4, 4, D_, D_, D_, D_, sDD, sDD, 1, H_, 1, H_, 1, 0, 0,
        1, sDD, 1, 0, 1.0f);

    // 2) P[h] = Wo'[h] @ WvT[h]^T
    mma_gemm<1><<<nsm, blk, SMEM_T>>>(Wop_hi, Wop_lo, WvT_hi, WvT_lo,
        nullptr, P_hi, P_lo,
        128, 4, 4, D_, D_, D_, D_, sDD, sDD, 1, H_, 1, H_, 1, 0, 0,
        1, sDD, 1, 0, 1.0f);

    // 3) t[b,h] = q[b] @ MT[h]^T   (ntiles = 4*16*16 = 1024)
    mma_gemm<1><<<nsm, blk, SMEM_T>>>(q_hi, q_lo, MT_hi, MT_lo,
        nullptr, t_hi, t_lo,
        1024, 4, 16, D_, D_, D_, D_, sLD, sDD, H_, B_, 1, H_, 1, 0, 0,
        1, sLD, 1, 0, 1.0f);

    // 4) scores[b,h] = t[b,h] @ k[b]^T / sqrt(D)   (ntiles = 16*16*16 = 4096)
    mma_gemm<0><<<nsm, blk, SMEM_T>>>(t_hi, t_lo, k_hi, k_lo,
        attn, nullptr, nullptr,
        4096, 16, 16, D_, D_, D_, L_, sLD, sLD, 1, B_ * H_, H_, B_, 1, 0, 0,
        1, sLL, 1, 0, inv_sqrt_d);

    // 5) ZT[b, e, h*L+m] = P[h] @ v[b]^T   (ntiles = 16*4*16 = 1024)
    mma_gemm<1><<<nsm, blk, SMEM_T>>>(P_hi, P_lo, v_hi, v_lo,
        nullptr, ZT_hi, ZT_lo,
        1024, 16, 4, D_, D_, D_, H_ * L_, sDD, sLD, 1, H_, H_, B_, 1, 0, 0,
        H_, (long)D_ * H_ * L_, H_, (long)L_, 1.0f);

    // 6) softmax in place + bf16 hi/lo in permuted [b,l,h,m] layout
    softmax_split<<<B_ * H_ * L_, blk>>>(attn, (uint32_t*)at_hi, (uint32_t*)at_lo);

    // 7) out partials: split-K=8 over H*L (ntiles = 4*16*16 = 1024)
    //    z = b*KS + ks: A = at'[b] + ks*2048 (lda=H*L), B = ZT[b] + ks*2048
    mma_gemm<0><<<nsm, blk, SMEM_T>>>(at_hi, at_lo, ZT_hi, ZT_lo,
        part, nullptr, nullptr,
        1024, 4, 16, (H_ * L_) / KS_, H_ * L_, H_ * L_, D_,
        (long)L_ * H_ * L_, (long)D_ * H_ * L_, KS_, B_, KS_, B_,
        KS_, (H_ * L_) / KS_, (H_ * L_) / KS_,
        1, sLD, 1, 0, 1.0f);

    // 8) reduce partials -> out
    reduce_part<<<(B_ * L_ * D_ / 4) / 256, blk>>>((const float4*)part, (float4*)out);
}

// round 8
// speedup vs baseline: 1.4652x; 1.0067x over previous
#include <cuda_runtime.h>
#include <cuda_bf16.h>
#include <stdint.h>
#include <math.h>

#define B_  2
#define L_  2048
#define D_  512
#define H_  8
#define HD_ 64
#define KS_ 8

// ======================= scratch (device globals) ==========================
__device__ __nv_bfloat16 g_q_hi [(size_t)B_*L_*D_];
__device__ __nv_bfloat16 g_q_lo [(size_t)B_*L_*D_];
__device__ __nv_bfloat16 g_k_hi [(size_t)B_*L_*D_];
__device__ __nv_bfloat16 g_k_lo [(size_t)B_*L_*D_];
__device__ __nv_bfloat16 g_v_hi [(size_t)B_*L_*D_];
__device__ __nv_bfloat16 g_v_lo [(size_t)B_*L_*D_];
__device__ __nv_bfloat16 g_WqT_hi[(size_t)H_*D_*D_];
__device__ __nv_bfloat16 g_WqT_lo[(size_t)H_*D_*D_];
__device__ __nv_bfloat16 g_WkT_hi[(size_t)H_*D_*D_];
__device__ __nv_bfloat16 g_WkT_lo[(size_t)H_*D_*D_];
__device__ __nv_bfloat16 g_WvT_hi[(size_t)H_*D_*D_];
__device__ __nv_bfloat16 g_WvT_lo[(size_t)H_*D_*D_];
__device__ __nv_bfloat16 g_Wop_hi[(size_t)H_*D_*D_];
__device__ __nv_bfloat16 g_Wop_lo[(size_t)H_*D_*D_];
__device__ __nv_bfloat16 g_MT_hi[(size_t)H_*D_*D_];
__device__ __nv_bfloat16 g_MT_lo[(size_t)H_*D_*D_];
__device__ __nv_bfloat16 g_P_hi [(size_t)H_*D_*D_];
__device__ __nv_bfloat16 g_P_lo [(size_t)H_*D_*D_];
__device__ __nv_bfloat16 g_t_hi [(size_t)B_*H_*L_*D_];
__device__ __nv_bfloat16 g_t_lo [(size_t)B_*H_*L_*D_];
__device__ __nv_bfloat16 g_ZT_hi[(size_t)B_*D_*H_*L_];
__device__ __nv_bfloat16 g_ZT_lo[(size_t)B_*D_*H_*L_];
__device__ __nv_bfloat16 g_at_hi[(size_t)B_*L_*H_*L_];
__device__ __nv_bfloat16 g_at_lo[(size_t)B_*L_*H_*L_];
__device__ float         g_part [(size_t)B_*KS_*L_*D_];

// ======================= small helpers ======================================
__device__ __forceinline__ uint32_t smem_u32(const void* p) {
    uint32_t a;
    asm("{ .reg .u64 t; cvta.to.shared.u64 t, %1; cvt.u32.u64 %0, t; }"
        : "=r"(a) : "l"(p));
    return a;
}
__device__ __forceinline__ uint32_t swz128(uint32_t o) { return o ^ ((o >> 3) & 0x70); }

__device__ __forceinline__ void cp16(uint32_t s, const void* g) {
    asm volatile("cp.async.cg.shared.global [%0], [%1], 16;" :: "r"(s), "l"(g));
}
#define CP_COMMIT() asm volatile("cp.async.commit_group;" ::: "memory")

__device__ __forceinline__ void ldm4(uint32_t* r, uint32_t a) {
    asm volatile("ldmatrix.sync.aligned.m8n8.x4.shared.b16 {%0,%1,%2,%3}, [%4];"
                 : "=r"(r[0]), "=r"(r[1]), "=r"(r[2]), "=r"(r[3]) : "r"(a));
}
__device__ __forceinline__ void mma_bf16(float* c, const uint32_t* a, const uint32_t* b) {
    asm volatile("mma.sync.aligned.m16n8k16.row.col.f32.bf16.bf16.f32 "
                 "{%0,%1,%2,%3}, {%4,%5,%6,%7}, {%8,%9}, {%0,%1,%2,%3};"
                 : "+f"(c[0]), "+f"(c[1]), "+f"(c[2]), "+f"(c[3])
                 : "r"(a[0]), "r"(a[1]), "r"(a[2]), "r"(a[3]), "r"(b[0]), "r"(b[1]));
}
__device__ __forceinline__ void split2(float x, __nv_bfloat16& h, __nv_bfloat16& l) {
    h = __float2bfloat16(x);
    l = __float2bfloat16(x - __bfloat162float(h));
}
__device__ __forceinline__ void split_pack(float2 v, uint32_t& hi, uint32_t& lo) {
    __nv_bfloat16 h0, l0, h1, l1;
    split2(v.x, h0, l0);
    split2(v.y, h1, l1);
    hi = ((uint32_t)__bfloat16_as_ushort(h1) << 16) | __bfloat16_as_ushort(h0);
    lo = ((uint32_t)__bfloat16_as_ushort(l1) << 16) | __bfloat16_as_ushort(l0);
}

// =============== persistent bf16x3 HMMA GEMM (KC=64, 3-stage) ===============
// C[m,n] = alpha * sum_k A[m,k]*B[n,k]  (NT; A rows stride lda, B rows stride ldb)
// Tile t -> (z, ty, tx):  z = t/(gx*gy), ty = (t%(gx*gy))/gx, tx = t%gx
// A offset: ((z/adiv)%amod)*sA + (z%azmod)*sA2 + ty*128*lda
// B offset: ((z/bdiv)%bmod)*sB + (z%azmod)*sB2 + tx*128*ldb
// C offset: (z/czdiv)*sC1 + (z%czmod)*sC2 + ty*128*ldc + tx*128
#define KC       64
#define TILE_B   (128 * 128)
#define STAGE_B  (4 * TILE_B)
#define NSTAGE   3
#define SMEM_T   (NSTAGE * STAGE_B)   // 192 KB

struct TileP {
    const __nv_bfloat16 *ah, *al, *bh, *bl;
    long coff;
};

template <int MODE>   // 0: fp32 out, 1: bf16 hi/lo out
__global__ __launch_bounds__(256, 1)
void mma_gemm(const __nv_bfloat16* __restrict__ Ahi, const __nv_bfloat16* __restrict__ Alo,
              const __nv_bfloat16* __restrict__ Bhi, const __nv_bfloat16* __restrict__ Blo,
              float* __restrict__ C, __nv_bfloat16* __restrict__ Chi,
              __nv_bfloat16* __restrict__ Clo,
              int ntiles, int gx, int gy,
              int K, int lda, int ldb, int ldc,
              long sA, long sB, int adiv, int amod, int bdiv, int bmod,
              int azmod, long sA2, long sB2,
              int czdiv, long sC1, int czmod, long sC2, float alpha)
{
    extern __shared__ char smem[];
    const uint32_t sb = smem_u32(smem);
    const int tid  = threadIdx.x;
    const int lane = tid & 31, wid = tid >> 5;
    const int moff = (wid & 1) * 64;
    const int noff = (wid >> 1) * 32;

    int t0 = blockIdx.x;
    if (t0 >= ntiles) return;

    auto tileinfo = [&](int t) -> TileP {
        const int gxy = gx * gy;
        const int z = t / gxy;
        const int r = t - z * gxy;
        const int ty = r / gx;
        const int tx = r - ty * gx;
        const long aoff = (long)((z / adiv) % amod) * sA + (long)(z % azmod) * sA2
                          + (long)ty * 128 * lda;
        const long boff = (long)((z / bdiv) % bmod) * sB + (long)(z % azmod) * sB2
                          + (long)tx * 128 * ldb;
        TileP p;
        p.ah = Ahi + aoff;  p.al = Alo + aoff;
        p.bh = Bhi + boff;  p.bl = Blo + boff;
        p.coff = (long)(z / czdiv) * sC1 + (long)(z % czmod) * sC2
                 + (long)ty * 128 * ldc + (long)tx * 128;
        return p;
    };

#define LOADT(T, cidx, stg) do {                                                 \
        const uint32_t st = sb + (stg) * STAGE_B;                                \
        const int k0 = (cidx) * KC;                                              \
        _Pragma("unroll")                                                        \
        for (int it = 0; it < 4; it++) {                                         \
            const int idx = tid + it * 256;                                      \
            const int row = idx >> 3, ch = idx & 7;                              \
            const uint32_t so = swz128(row * 128 + ch * 16);                     \
            const long goA = (long)row * lda + k0 + ch * 8;                      \
            const long goB = (long)row * ldb + k0 + ch * 8;                      \
            cp16(st + so,              (T).ah + goA);                            \
            cp16(st + TILE_B + so,     (T).al + goA);                            \
            cp16(st + 2 * TILE_B + so, (T).bh + goB);                            \
            cp16(st + 3 * TILE_B + so, (T).bl + goB);                            \
        }                                                                        \
    } while (0)

    const int NC = K / KC;
    const int stride = gridDim.x;

    TileP cur = tileinfo(t0);
    LOADT(cur, 0, 0); CP_COMMIT();
    LOADT(cur, 1, 1); CP_COMMIT();
    int lstage = 2;
    int cstage = 0;

    const int arow = (lane & 7) + ((lane >> 3) & 1) * 8;
    const int ach  = (lane >> 4);
    const int brow = (lane & 7) + ((lane >> 4) & 1) * 8;
    const int bch  = ((lane >> 3) & 1);
    const int gq = lane >> 2, tg = lane & 3;

    for (int t = t0; t < ntiles; t += stride) {
        const int tn = t + stride;
        const bool has_next = tn < ntiles;
        TileP nxt = has_next ? tileinfo(tn) : cur;

        float acc[4][4][4];
#pragma unroll
        for (int a = 0; a < 4; a++)
#pragma unroll
            for (int b = 0; b < 4; b++)
#pragma unroll
                for (int c = 0; c < 4; c++) acc[a][b][c] = 0.f;

        for (int c = 0; c < NC; c++) {
            asm volatile("cp.async.wait_group 1;" ::: "memory");
            __syncthreads();
            const int cc = c + 2;
            if (cc < NC) {
                LOADT(cur, cc, lstage);
            } else if (has_next && cc - NC < 2) {
                LOADT(nxt, cc - NC, lstage);
            }
            CP_COMMIT();
            lstage = (lstage == 2) ? 0 : lstage + 1;

            const uint32_t st = sb + cstage * STAGE_B;
            cstage = (cstage == 2) ? 0 : cstage + 1;
#pragma unroll
            for (int kk = 0; kk < 4; kk++) {
                uint32_t ah[4][4], al[4][4], bh[4][2], bl[4][2];
#pragma unroll
                for (int mf = 0; mf < 4; mf++) {
                    uint32_t ad = st + swz128((moff + mf * 16 + arow) * 128 + (kk * 2 + ach) * 16);
                    ldm4(ah[mf], ad);
                    ldm4(al[mf], ad + TILE_B);
                }
#pragma unroll
                for (int p = 0; p < 2; p++) {
                    uint32_t bd = st + 2 * TILE_B +
                                  swz128((noff + p * 16 + brow) * 128 + (kk * 2 + bch) * 16);
                    uint32_t r[4];
                    ldm4(r, bd);
                    bh[2 * p][0] = r[0]; bh[2 * p][1] = r[1];
                    bh[2 * p + 1][0] = r[2]; bh[2 * p + 1][1] = r[3];
                    ldm4(r, bd + TILE_B);
                    bl[2 * p][0] = r[0]; bl[2 * p][1] = r[1];
                    bl[2 * p + 1][0] = r[2]; bl[2 * p + 1][1] = r[3];
                }
#pragma unroll
                for (int mf = 0; mf < 4; mf++)
#pragma unroll
                    for (int nf = 0; nf < 4; nf++) {
                        mma_bf16(acc[mf][nf], ah[mf], bh[nf]);
                        mma_bf16(acc[mf][nf], ah[mf], bl[nf]);
                        mma_bf16(acc[mf][nf], al[mf], bh[nf]);
                    }
            }
        }

        // ---- epilogue (overlaps next tile's in-flight stage loads) ----
#pragma unroll
        for (int mf = 0; mf < 4; mf++)
#pragma unroll
            for (int nf = 0; nf < 4; nf++) {
                const long row = moff + mf * 16 + gq;
                const long col = noff + nf * 8 + tg * 2;
                float v0 = alpha * acc[mf][nf][0];
                float v1 = alpha * acc[mf][nf][1];
                float v2 = alpha * acc[mf][nf][2];
                float v3 = alpha * acc[mf][nf][3];
                if (MODE == 0) {
                    float2 p0 = {v0, v1}, p1 = {v2, v3};
                    *reinterpret_cast<float2*>(C + cur.coff + row * ldc + col)       = p0;
                    *reinterpret_cast<float2*>(C + cur.coff + (row + 8) * ldc + col) = p1;
                } else {
                    uint32_t hp0, lp0, hp1, lp1;
                    split_pack({v0, v1}, hp0, lp0);
                    split_pack({v2, v3}, hp1, lp1);
                    *reinterpret_cast<uint32_t*>(Chi + cur.coff + row * ldc + col)       = hp0;
                    *reinterpret_cast<uint32_t*>(Clo + cur.coff + row * ldc + col)       = lp0;
                    *reinterpret_cast<uint32_t*>(Chi + cur.coff + (row + 8) * ldc + col) = hp1;
                    *reinterpret_cast<uint32_t*>(Clo + cur.coff + (row + 8) * ldc + col) = lp1;
                }
            }
        cur = nxt;
    }
#undef LOADT
}

// ======================= helper kernels =====================================
// merged q/k/v split: blockIdx.y selects tensor
__global__ __launch_bounds__(256)
void split_qkv(const float4* __restrict__ q, const float4* __restrict__ k,
               const float4* __restrict__ v,
               uint2* __restrict__ qh, uint2* __restrict__ ql,
               uint2* __restrict__ kh, uint2* __restrict__ kl,
               uint2* __restrict__ vh, uint2* __restrict__ vl, int n4)
{
    int i = blockIdx.x * 256 + threadIdx.x;
    if (i >= n4) return;
    const int sel = blockIdx.y;
    const float4* s = (sel == 0) ? q : (sel == 1) ? k : v;
    uint2* hi = (sel == 0) ? qh : (sel == 1) ? kh : vh;
    uint2* lo = (sel == 0) ? ql : (sel == 1) ? kl : vl;
    float4 x = s[i];
    __nv_bfloat16 h[4], l[4];
    split2(x.x, h[0], l[0]);
    split2(x.y, h[1], l[1]);
    split2(x.z, h[2], l[2]);
    split2(x.w, h[3], l[3]);
    hi[i] = *reinterpret_cast<uint2*>(h);
    lo[i] = *reinterpret_cast<uint2*>(l);
}

// merged Wq/Wk/Wv transpose-split: blockIdx.z = w*8 + head
__global__ __launch_bounds__(256)
void transpose_split_w3(const float* __restrict__ Wq, const float* __restrict__ Wk,
                        const float* __restrict__ Wv,
                        __nv_bfloat16* __restrict__ qhi, __nv_bfloat16* __restrict__ qlo,
                        __nv_bfloat16* __restrict__ khi, __nv_bfloat16* __restrict__ klo,
                        __nv_bfloat16* __restrict__ vhi, __nv_bfloat16* __restrict__ vlo)
{
    __shared__ float t[32][33];
    const int zz = blockIdx.z;
    const int w = zz >> 3, z = zz & 7;
    const float* src = (w == 0) ? Wq : (w == 1) ? Wk : Wv;
    __nv_bfloat16* hi = (w == 0) ? qhi : (w == 1) ? khi : vhi;
    __nv_bfloat16* lo = (w == 0) ? qlo : (w == 1) ? klo : vlo;

    const int e0 = blockIdx.y * 32, d0 = blockIdx.x * 32;
    const int tx = threadIdx.x & 31, ty = threadIdx.x >> 5;
    const float* s = src + (long)z * D_ * D_;
#pragma unroll
    for (int r = 0; r < 32; r += 8)
        t[ty + r][tx] = s[(long)(e0 + ty + r) * D_ + d0 + tx];
    __syncthreads();
    const long base = (long)z * D_ * D_;
#pragma unroll
    for (int r = 0; r < 32; r += 8) {
        float x = t[tx][ty + r];
        __nv_bfloat16 h, l;
        split2(x, h, l);
        long o = base + (long)(d0 + ty + r) * D_ + e0 + tx;
        hi[o] = h; lo[o] = l;
    }
}

__global__ __launch_bounds__(256)
void wo_permute_split(const float* __restrict__ Wo,
                      __nv_bfloat16* __restrict__ hi, __nv_bfloat16* __restrict__ lo)
{
    long idx = (long)blockIdx.x * 256 + threadIdx.x;
    int f = (int)(idx & 511);
    int e = (int)((idx >> 9) & 511);
    int h = (int)(idx >> 18);
    float x = Wo[(long)e * (H_ * D_) + (f >> 6) * 512 + h * 64 + (f & 63)];
    __nv_bfloat16 hb, lb;
    split2(x, hb, lb);
    hi[idx] = hb; lo[idx] = lb;
}

// softmax over rows of 2048 in place (fp32, [b,h,l,m]) + bf16 hi/lo in [b,l,h,m]
__global__ __launch_bounds__(256)
void softmax_split(float* __restrict__ data,
                   uint32_t* __restrict__ hi, uint32_t* __restrict__ lo)
{
    const int r = blockIdx.x;
    const int b = r >> 14;
    const int h = (r >> 11) & (H_ - 1);
    const int l = r & (L_ - 1);
    float2* p = reinterpret_cast<float2*>(data + (long)r * L_);
    const long ob2 = ((((long)b * L_ + l) * H_ + h) * L_) >> 1;
    const int tid = threadIdx.x;

    float2 vals[4];
    float vmax = -1e30f;
#pragma unroll
    for (int i = 0; i < 4; i++) {
        vals[i] = p[tid + i * 256];
        vmax = fmaxf(vmax, fmaxf(vals[i].x, vals[i].y));
    }
#pragma unroll
    for (int o = 16; o > 0; o >>= 1) vmax = fmaxf(vmax, __shfl_xor_sync(0xFFFFFFFFu, vmax, o));

    __shared__ float smax[8], ssum[8];
    if ((tid & 31) == 0) smax[tid >> 5] = vmax;
    __syncthreads();
    float m = smax[0];
#pragma unroll
    for (int i = 1; i < 8; i++) m = fmaxf(m, smax[i]);

    float sum = 0.f;
#pragma unroll
    for (int i = 0; i < 4; i++) {
        vals[i].x = __expf(vals[i].x - m);
        vals[i].y = __expf(vals[i].y - m);
        sum += vals[i].x + vals[i].y;
    }
#pragma unroll
    for (int o = 16; o > 0; o >>= 1) sum += __shfl_xor_sync(0xFFFFFFFFu, sum, o);
    if ((tid & 31) == 0) ssum[tid >> 5] = sum;
    __syncthreads();
    float tot = 0.f;
#pragma unroll
    for (int i = 0; i < 8; i++) tot += ssum[i];
    const float inv = 1.f / tot;
#pragma unroll
    for (int i = 0; i < 4; i++) {
        float2 y = {vals[i].x * inv, vals[i].y * inv};
        p[tid + i * 256] = y;
        uint32_t hp, lp;
        split_pack(y, hp, lp);
        hi[ob2 + tid + i * 256] = hp;
        lo[ob2 + tid + i * 256] = lp;
    }
}

// reduce partials: out[b][j] = sum_ks part[b*KS+ks][j]
__global__ __launch_bounds__(256)
void reduce_part(const float4* __restrict__ part, float4* __restrict__ out)
{
    const int LD4 = L_ * D_ / 4;
    long idx = (long)blockIdx.x * 256 + threadIdx.x;
    int b = (int)(idx / LD4);
    long j = idx - (long)b * LD4;
    const float4* p = part + (long)b * KS_ * LD4 + j;
    float4 s = p[0];
#pragma unroll
    for (int ks = 1; ks < KS_; ks++) {
        float4 t = p[(long)ks * LD4];
        s.x += t.x; s.y += t.y; s.z += t.z; s.w += t.w;
    }
    out[idx] = s;
}

// ======================= launch =============================================
extern "C" void kernel_launch(void* const* d_in, const int* in_sizes, int n_in,
                              void* d_out, int out_size)
{
    const float* q  = (const float*)d_in[0];
    const float* k  = (const float*)d_in[1];
    const float* v  = (const float*)d_in[2];
    const float* Wq = (const float*)d_in[3];
    const float* Wk = (const float*)d_in[4];
    const float* Wv = (const float*)d_in[5];
    const float* Wo = (const float*)d_in[6];

    float* out  = (float*)d_out;
    float* attn = out + (long)B_ * L_ * D_;

    static int nsm = 0;
    if (!nsm) {
        cudaDeviceGetAttribute(&nsm, cudaDevAttrMultiProcessorCount, 0);
        cudaFuncSetAttribute(mma_gemm<0>, cudaFuncAttributeMaxDynamicSharedMemorySize, SMEM_T);
        cudaFuncSetAttribute(mma_gemm<1>, cudaFuncAttributeMaxDynamicSharedMemorySize, SMEM_T);
        if (nsm <= 0) nsm = 148;
    }

#define SYM(p, s) cudaGetSymbolAddress((void**)&p, s)
    __nv_bfloat16 *q_hi, *q_lo, *k_hi, *k_lo, *v_hi, *v_lo;
    __nv_bfloat16 *WqT_hi, *WqT_lo, *WkT_hi, *WkT_lo, *WvT_hi, *WvT_lo, *Wop_hi, *Wop_lo;
    __nv_bfloat16 *MT_hi, *MT_lo, *P_hi, *P_lo;
    __nv_bfloat16 *t_hi, *t_lo, *ZT_hi, *ZT_lo, *at_hi, *at_lo;
    float *part;
    SYM(q_hi, g_q_hi);  SYM(q_lo, g_q_lo);
    SYM(k_hi, g_k_hi);  SYM(k_lo, g_k_lo);
    SYM(v_hi, g_v_hi);  SYM(v_lo, g_v_lo);
    SYM(WqT_hi, g_WqT_hi); SYM(WqT_lo, g_WqT_lo);
    SYM(WkT_hi, g_WkT_hi); SYM(WkT_lo, g_WkT_lo);
    SYM(WvT_hi, g_WvT_hi); SYM(WvT_lo, g_WvT_lo);
    SYM(Wop_hi, g_Wop_hi); SYM(Wop_lo, g_Wop_lo);
    SYM(MT_hi, g_MT_hi);   SYM(MT_lo, g_MT_lo);
    SYM(P_hi, g_P_hi);     SYM(P_lo, g_P_lo);
    SYM(t_hi, g_t_hi);     SYM(t_lo, g_t_lo);
    SYM(ZT_hi, g_ZT_hi);   SYM(ZT_lo, g_ZT_lo);
    SYM(at_hi, g_at_hi);   SYM(at_lo, g_at_lo);
    SYM(part, g_part);
#undef SYM

    const long sLD = (long)L_ * D_;
    const long sLL = (long)L_ * L_;
    const long sDD = (long)D_ * D_;
    const float inv_sqrt_d = 1.0f / sqrtf((float)D_);

    dim3 blk(256);
    const int n4_in = (B_ * L_ * D_) / 4;

    // launch 0: merged q/k/v splits
    dim3 gsp((n4_in + 255) / 256, 3);
    split_qkv<<<gsp, blk>>>((const float4*)q, (const float4*)k, (const float4*)v,
        (uint2*)q_hi, (uint2*)q_lo, (uint2*)k_hi, (uint2*)k_lo,
        (uint2*)v_hi, (uint2*)v_lo, n4_in);

    // launch 1: merged Wq/Wk/Wv transpose-splits
    dim3 gtw(D_ / 32, D_ / 32, 3 * H_);
    transpose_split_w3<<<gtw, blk>>>(Wq, Wk, Wv,
        WqT_hi, WqT_lo, WkT_hi, WkT_lo, WvT_hi, WvT_lo);

    // launch 2: Wo permute-split
    wo_permute_split<<<(H_ * D_ * D_) / 256, blk>>>(Wo, Wop_hi, Wop_lo);

    // launch 3: MT[h] = WkT[h] @ WqT[h]^T   (128 tiles)
    mma_gemm<1><<<nsm, blk, SMEM_T>>>(WkT_hi, WkT_lo, WqT_hi, WqT_lo,
        nullptr, MT_hi, MT_lo,
        128, 4, 4, D_, D_, D_, D_, sDD, sDD, 1, H_, 1, H_, 1, 0, 0,
        1, sDD, 1, 0, 1.0f);

    // launch 4: P[h] = Wo'[h] @ WvT[h]^T   (128 tiles)
    mma_gemm<1><<<nsm, blk, SMEM_T>>>(Wop_hi, Wop_lo, WvT_hi, WvT_lo,
        nullptr, P_hi, P_lo,
        128, 4, 4, D_, D_, D_, D_, sDD, sDD, 1, H_, 1, H_, 1, 0, 0,
        1, sDD, 1, 0, 1.0f);

    // launch 5 (ncu captures this one): t[b,h] = q[b] @ MT[h]^T   (1024 tiles)
    mma_gemm<1><<<nsm, blk, SMEM_T>>>(q_hi, q_lo, MT_hi, MT_lo,
        nullptr, t_hi, t_lo,
        1024, 4, 16, D_, D_, D_, D_, sLD, sDD, H_, B_, 1, H_, 1, 0, 0,
        1, sLD, 1, 0, 1.0f);

    // launch 6: scores[b,h] = t[b,h] @ k[b]^T / sqrt(D)   (4096 tiles)
    mma_gemm<0><<<nsm, blk, SMEM_T>>>(t_hi, t_lo, k_hi, k_lo,
        attn, nullptr, nullptr,
        4096, 16, 16, D_, D_, D_, L_, sLD, sLD, 1, B_ * H_, H_, B_, 1, 0, 0,
        1, sLL, 1, 0, inv_sqrt_d);

    // launch 7: ZT[b, e, h*L+m] = P[h] @ v[b]^T   (1024 tiles)
    mma_gemm<1><<<nsm, blk, SMEM_T>>>(P_hi, P_lo, v_hi, v_lo,
        nullptr, ZT_hi, ZT_lo,
        1024, 16, 4, D_, D_, D_, H_ * L_, sDD, sLD, 1, H_, H_, B_, 1, 0, 0,
        H_, (long)D_ * H_ * L_, H_, (long)L_, 1.0f);

    // launch 8: softmax in place + bf16 hi/lo in permuted [b,l,h,m] layout
    softmax_split<<<B_ * H_ * L_, blk>>>(attn, (uint32_t*)at_hi, (uint32_t*)at_lo);

    // launch 9: out partials, split-K=8 over H*L (1024 tiles)
    mma_gemm<0><<<nsm, blk, SMEM_T>>>(at_hi, at_lo, ZT_hi, ZT_lo,
        part, nullptr, nullptr,
        1024, 4, 16, (H_ * L_) / KS_, H_ * L_, H_ * L_, D_,
        (long)L_ * H_ * L_, (long)D_ * H_ * L_, KS_, B_, KS_, B_,
        KS_, (H_ * L_) / KS_, (H_ * L_) / KS_,
        1, sLD, 1, 0, 1.0f);

    // launch 10: reduce partials -> out
    reduce_part<<<(B_ * L_ * D_ / 4) / 256, blk>>>((const float4*)part, (float4*)out);
}